// round 3
// baseline (speedup 1.0000x reference)
#include <cuda_runtime.h>
#include <cuda_bf16.h>
#include <math.h>

// ---------------------------------------------------------------------------
// Problem constants
// ---------------------------------------------------------------------------
#define BATCH 4
#define SEQ 64
#define PAST 2048
#define TTOT 2112            // PAST + SEQ
#define HIDDEN 2048
#define NQ 16
#define NKV 4
#define HDIM 128
#define INTER 8192
#define VOCAB 32000
#define ROWS 256             // B*S
#define EPS 1e-6f

#define LOGITS_ELEMS (ROWS * VOCAB)                  // 8,192,000
#define GATHERED_ELEMS (ROWS * HIDDEN)               // 524,288
#define PRESENT_OFF (LOGITS_ELEMS + GATHERED_ELEMS)  // 8,716,288

// ---------------------------------------------------------------------------
// Scratch (device globals; no runtime allocation)
// ---------------------------------------------------------------------------
__device__ float g_hs[ROWS * HIDDEN];
__device__ float g_normed[ROWS * 2 * HIDDEN];
__device__ float g_q[ROWS * NQ * HDIM];
__device__ float g_k[ROWS * NKV * HDIM];
__device__ float g_v[ROWS * NKV * HDIM];
__device__ float g_attn[ROWS * NQ * HDIM];
__device__ float g_hn[ROWS * HIDDEN];
__device__ float g_gate[ROWS * INTER];
__device__ float g_act[ROWS * INTER];
__device__ float g_fn[ROWS * HIDDEN];

// ---------------------------------------------------------------------------
// Block reductions (256 threads)
// ---------------------------------------------------------------------------
__device__ __forceinline__ float block_sum(float v) {
    __shared__ float sh[8];
    __shared__ float total;
    int tid = threadIdx.x;
#pragma unroll
    for (int o = 16; o > 0; o >>= 1) v += __shfl_xor_sync(0xffffffffu, v, o);
    if ((tid & 31) == 0) sh[tid >> 5] = v;
    __syncthreads();
    if (tid == 0) {
        float s = 0.f;
#pragma unroll
        for (int i = 0; i < 8; i++) s += sh[i];
        total = s;
    }
    __syncthreads();
    float r = total;
    __syncthreads();   // allow re-entry
    return r;
}

__device__ __forceinline__ float block_max(float v) {
    __shared__ float sh[8];
    __shared__ float total;
    int tid = threadIdx.x;
#pragma unroll
    for (int o = 16; o > 0; o >>= 1) v = fmaxf(v, __shfl_xor_sync(0xffffffffu, v, o));
    if ((tid & 31) == 0) sh[tid >> 5] = v;
    __syncthreads();
    if (tid == 0) {
        float s = -INFINITY;
#pragma unroll
        for (int i = 0; i < 8; i++) s = fmaxf(s, sh[i]);
        total = s;
    }
    __syncthreads();
    float r = total;
    __syncthreads();
    return r;
}

// ---------------------------------------------------------------------------
// Tiled SGEMM 128x128x8, 256 threads, 8x8 per thread, fp32.
// C[M,N] = A[M,K] @ B[K,N]  (+ epilogue)
//   EPI 0: C = acc
//   EPI 1: C = acc + Aux   (residual, Aux same layout as C; Aux may alias C)
//   EPI 2: C = silu(Aux) * acc
// Requires: M % 128 == 0, N % 128 == 0, K % 8 == 0.
// ---------------------------------------------------------------------------
template <int EPI>
__global__ void __launch_bounds__(256) sgemm128(
    const float* __restrict__ A, const float* __restrict__ B,
    float* __restrict__ C, const float* __restrict__ Aux,
    int M, int N, int K)
{
    __shared__ float As[8][128];
    __shared__ float Bs[8][128];

    const int bx = blockIdx.x;   // N block
    const int by = blockIdx.y;   // M block
    const int tid = threadIdx.x;

    const float* Ag = A + (size_t)by * 128 * K;
    const float* Bg = B + (size_t)bx * 128;

    const int aRow  = tid >> 1;          // 0..127
    const int aCol4 = (tid & 1) * 4;     // 0 or 4
    const int bRow  = tid >> 5;          // 0..7
    const int bCol4 = (tid & 31) * 4;    // 0..124

    const int tRow = (tid >> 4) * 8;
    const int tCol = (tid & 15) * 8;

    float acc[8][8];
#pragma unroll
    for (int i = 0; i < 8; i++)
#pragma unroll
        for (int j = 0; j < 8; j++) acc[i][j] = 0.f;

    for (int k0 = 0; k0 < K; k0 += 8) {
        float4 av = *reinterpret_cast<const float4*>(Ag + (size_t)aRow * K + k0 + aCol4);
        float4 bv = *reinterpret_cast<const float4*>(Bg + (size_t)(k0 + bRow) * N + bCol4);
        __syncthreads();
        As[aCol4 + 0][aRow] = av.x;
        As[aCol4 + 1][aRow] = av.y;
        As[aCol4 + 2][aRow] = av.z;
        As[aCol4 + 3][aRow] = av.w;
        *reinterpret_cast<float4*>(&Bs[bRow][bCol4]) = bv;
        __syncthreads();
#pragma unroll
        for (int k = 0; k < 8; k++) {
            float ar[8], br[8];
            float4 a0 = *reinterpret_cast<const float4*>(&As[k][tRow]);
            float4 a1 = *reinterpret_cast<const float4*>(&As[k][tRow + 4]);
            float4 b0 = *reinterpret_cast<const float4*>(&Bs[k][tCol]);
            float4 b1 = *reinterpret_cast<const float4*>(&Bs[k][tCol + 4]);
            ar[0]=a0.x; ar[1]=a0.y; ar[2]=a0.z; ar[3]=a0.w;
            ar[4]=a1.x; ar[5]=a1.y; ar[6]=a1.z; ar[7]=a1.w;
            br[0]=b0.x; br[1]=b0.y; br[2]=b0.z; br[3]=b0.w;
            br[4]=b1.x; br[5]=b1.y; br[6]=b1.z; br[7]=b1.w;
#pragma unroll
            for (int i = 0; i < 8; i++)
#pragma unroll
                for (int j = 0; j < 8; j++)
                    acc[i][j] = fmaf(ar[i], br[j], acc[i][j]);
        }
    }

    const int cRowBase = by * 128 + tRow;
    const int cColBase = bx * 128 + tCol;
#pragma unroll
    for (int i = 0; i < 8; i++) {
        size_t roff = (size_t)(cRowBase + i) * N + cColBase;
        float* Crow = C + roff;
#pragma unroll
        for (int j = 0; j < 8; j++) {
            float v = acc[i][j];
            if constexpr (EPI == 1) {
                v += Aux[roff + j];
            } else if constexpr (EPI == 2) {
                float gv = Aux[roff + j];
                v = (gv / (1.f + expf(-gv))) * v;
            }
            Crow[j] = v;
        }
    }
}

// ---------------------------------------------------------------------------
// Dual RMS norm + concat: normed[row] = [rms(emb)*w_in , rms(hs)*w_hid]
// ---------------------------------------------------------------------------
__global__ void __launch_bounds__(256) rms_concat_kernel(
    const float* __restrict__ emb, const float* __restrict__ hs,
    const float* __restrict__ w_in, const float* __restrict__ w_hid,
    float* __restrict__ normed)
{
    const int row = blockIdx.x;
    const int tid = threadIdx.x;
    const float* x1 = emb + (size_t)row * HIDDEN;
    const float* x2 = hs + (size_t)row * HIDDEN;
    float s1 = 0.f, s2 = 0.f;
    for (int i = tid; i < HIDDEN; i += 256) {
        float a = x1[i]; s1 += a * a;
        float b = x2[i]; s2 += b * b;
    }
    float r1 = block_sum(s1);
    float r2 = block_sum(s2);
    float inv1 = rsqrtf(r1 / (float)HIDDEN + EPS);
    float inv2 = rsqrtf(r2 / (float)HIDDEN + EPS);
    float* o = normed + (size_t)row * (2 * HIDDEN);
    for (int i = tid; i < HIDDEN; i += 256) {
        o[i]          = x1[i] * inv1 * w_in[i];
        o[HIDDEN + i] = x2[i] * inv2 * w_hid[i];
    }
}

// ---------------------------------------------------------------------------
// Single RMS norm
// ---------------------------------------------------------------------------
__global__ void __launch_bounds__(256) rms_kernel(
    const float* __restrict__ x, const float* __restrict__ w, float* __restrict__ y)
{
    const int row = blockIdx.x;
    const int tid = threadIdx.x;
    const float* xr = x + (size_t)row * HIDDEN;
    float s = 0.f;
    for (int i = tid; i < HIDDEN; i += 256) { float a = xr[i]; s += a * a; }
    float r = block_sum(s);
    float inv = rsqrtf(r / (float)HIDDEN + EPS);
    float* yr = y + (size_t)row * HIDDEN;
    for (int i = tid; i < HIDDEN; i += 256) yr[i] = xr[i] * inv * w[i];
}

// ---------------------------------------------------------------------------
// Gather by last_token_ids, write `gathered` output, and final RMS -> fn
// ---------------------------------------------------------------------------
__global__ void __launch_bounds__(256) gather_rms_kernel(
    const float* __restrict__ hs, const int* __restrict__ lt,
    const float* __restrict__ w, float* __restrict__ out_gathered,
    float* __restrict__ fn)
{
    const int row = blockIdx.x;   // b*SEQ + s
    const int tid = threadIdx.x;
    const int b = row >> 6;
    const int src_s = lt[row];
    const float* x = hs + ((size_t)b * SEQ + src_s) * HIDDEN;
    float s = 0.f;
    for (int i = tid; i < HIDDEN; i += 256) { float a = x[i]; s += a * a; }
    float r = block_sum(s);
    float inv = rsqrtf(r / (float)HIDDEN + EPS);
    float* og = out_gathered + (size_t)row * HIDDEN;
    float* fr = fn + (size_t)row * HIDDEN;
    for (int i = tid; i < HIDDEN; i += 256) {
        float a = x[i];
        og[i] = a;
        fr[i] = a * inv * w[i];
    }
}

// ---------------------------------------------------------------------------
// Copy past KV (B,2,NKV,PAST,128) into present (B,2,NKV,TTOT,128) output
// total float4 = 4*2*4*2048*128/4 = 2,097,152  -> grid 8192 x 256
// ---------------------------------------------------------------------------
__global__ void __launch_bounds__(256) copy_past_kernel(
    const float* __restrict__ past, float* __restrict__ present)
{
    const int idx = blockIdx.x * 256 + threadIdx.x;  // float4 index
    const int lane = idx & 31;
    const int row = idx >> 5;        // (b,c,h,t) with t fastest
    const int t = row & 2047;
    const int bch = row >> 11;
    const float4* src = reinterpret_cast<const float4*>(past) + idx;
    float4* dst = reinterpret_cast<float4*>(present) + ((size_t)bch * TTOT + t) * 32 + lane;
    *dst = *src;
}

// ---------------------------------------------------------------------------
// RoPE q (in place), RoPE k -> present, copy v -> present
// grid (256, 24), block 64
// ---------------------------------------------------------------------------
__global__ void __launch_bounds__(64) rope_store_kernel(
    float* __restrict__ q, const float* __restrict__ k, const float* __restrict__ v,
    const float* __restrict__ rope, const int* __restrict__ pos_ids,
    float* __restrict__ present)
{
    const int bs = blockIdx.x;
    const int h = blockIdx.y;
    const int d = threadIdx.x;     // 0..63
    const int b = bs >> 6, s = bs & 63;
    const int pos = pos_ids[bs];
    const float c = rope[(size_t)pos * 128 + d];
    const float sn = rope[(size_t)pos * 128 + 64 + d];
    if (h < 16) {
        float* base = q + ((size_t)bs * NQ + h) * HDIM;
        float x1 = base[d], x2 = base[d + 64];
        base[d] = x1 * c - x2 * sn;
        base[d + 64] = x2 * c + x1 * sn;
    } else if (h < 20) {
        const int kh = h - 16;
        const float* base = k + ((size_t)bs * NKV + kh) * HDIM;
        float x1 = base[d], x2 = base[d + 64];
        float* dst = present + (((size_t)(b * 2 + 0) * NKV + kh) * TTOT + PAST + s) * HDIM;
        dst[d] = x1 * c - x2 * sn;
        dst[d + 64] = x2 * c + x1 * sn;
    } else {
        const int vh = h - 20;
        const float* base = v + ((size_t)bs * NKV + vh) * HDIM;
        float* dst = present + (((size_t)(b * 2 + 1) * NKV + vh) * TTOT + PAST + s) * HDIM;
        dst[d] = base[d];
        dst[d + 64] = base[d + 64];
    }
}

// ---------------------------------------------------------------------------
// Attention: one block per (b, kvh, 32-query chunk). Online softmax over
// T = 2112 in 64-key tiles; K/V read from the `present` output region.
// 256 threads. Dynamic smem (padded tiles).
// ---------------------------------------------------------------------------
#define QS_STRIDE 132
#define SC_STRIDE 65
#define ATTN_SMEM ((32 * QS_STRIDE + 64 * QS_STRIDE + 64 * QS_STRIDE + 32 * SC_STRIDE + 64) * 4)

__global__ void __launch_bounds__(256) attn_kernel(
    const float* __restrict__ qbuf, const float* __restrict__ kv,
    const int* __restrict__ ctx_len, float* __restrict__ out)
{
    extern __shared__ float sm[];
    float* qs = sm;                        // 32 x 132
    float* ks = qs + 32 * QS_STRIDE;       // 64 x 132
    float* vs = ks + 64 * QS_STRIDE;       // 64 x 132
    float* sc = vs + 64 * QS_STRIDE;       // 32 x 65
    float* corr = sc + 32 * SC_STRIDE;     // 32
    float* lsm = corr + 32;                // 32

    const int tid = threadIdx.x;
    const int blk = blockIdx.x;
    const int qb = blk & 7;
    const int kvh = (blk >> 3) & 3;
    const int b = blk >> 5;

    // load Q tile (32 queries x 128)
    for (int i = tid; i < 32 * 128; i += 256) {
        int ql = i >> 7, d = i & 127;
        int qid = qb * 32 + ql;
        int gi = qid >> 6, s = qid & 63;
        qs[ql * QS_STRIDE + d] =
            qbuf[(((size_t)(b * SEQ + s)) * NQ + (kvh * 4 + gi)) * HDIM + d];
    }

    float acc[16];
#pragma unroll
    for (int i = 0; i < 16; i++) acc[i] = 0.f;
    float m = -INFINITY, l = 0.f;

    const float* Kb = kv + (((size_t)(b * 2 + 0)) * NKV + kvh) * TTOT * HDIM;
    const float* Vb = kv + (((size_t)(b * 2 + 1)) * NKV + kvh) * TTOT * HDIM;
    const int ctx = ctx_len[b];

    const int ql_s = tid >> 3;            // 0..31  (query for scores & AV)
    const int ktg = tid & 7;              // key group
    const int qid_s = qb * 32 + ql_s;
    const int s_q = qid_s & 63;
    const int dg = (tid & 7) * 16;        // dim group for AV

    for (int t0 = 0; t0 < TTOT; t0 += 64) {
        __syncthreads();
        // load K/V tiles
        for (int i = tid * 4; i < 64 * 128; i += 1024) {
            int r = i >> 7, d = i & 127;
            *reinterpret_cast<float4*>(&ks[r * QS_STRIDE + d]) =
                *reinterpret_cast<const float4*>(&Kb[(size_t)(t0 + r) * HDIM + d]);
            *reinterpret_cast<float4*>(&vs[r * QS_STRIDE + d]) =
                *reinterpret_cast<const float4*>(&Vb[(size_t)(t0 + r) * HDIM + d]);
        }
        __syncthreads();
        // scores: each thread: 1 query x 8 keys
        {
            const float* qrow = &qs[ql_s * QS_STRIDE];
#pragma unroll
            for (int j = 0; j < 8; j++) {
                int kt = ktg + 8 * j;
                const float* krow = &ks[kt * QS_STRIDE];
                float dot = 0.f;
#pragma unroll
                for (int d = 0; d < 128; d += 4) {
                    float4 qv = *reinterpret_cast<const float4*>(&qrow[d]);
                    float4 kk = *reinterpret_cast<const float4*>(&krow[d]);
                    dot = fmaf(qv.x, kk.x, dot);
                    dot = fmaf(qv.y, kk.y, dot);
                    dot = fmaf(qv.z, kk.z, dot);
                    dot = fmaf(qv.w, kk.w, dot);
                }
                int t = t0 + kt;
                bool valid = (t < PAST) ? (t < ctx) : ((t - PAST) <= s_q);
                sc[ql_s * SC_STRIDE + kt] =
                    valid ? dot * 0.08838834764831845f : -INFINITY;
            }
        }
        __syncthreads();
        // online softmax (one thread per query)
        if (tid < 32) {
            float mt = -INFINITY;
#pragma unroll 8
            for (int j = 0; j < 64; j++) mt = fmaxf(mt, sc[tid * SC_STRIDE + j]);
            float mnew = fmaxf(m, mt);
            float c, sum = 0.f;
            if (mnew == -INFINITY) {
                c = 1.f;
                for (int j = 0; j < 64; j++) sc[tid * SC_STRIDE + j] = 0.f;
            } else {
                c = __expf(m - mnew);
#pragma unroll 8
                for (int j = 0; j < 64; j++) {
                    float p = __expf(sc[tid * SC_STRIDE + j] - mnew);
                    sc[tid * SC_STRIDE + j] = p;
                    sum += p;
                }
            }
            l = l * c + sum;
            m = mnew;
            corr[tid] = c;
        }
        __syncthreads();
        // accumulate P @ V : each thread: 1 query x 16 dims
        {
            float c = corr[ql_s];
#pragma unroll
            for (int i = 0; i < 16; i++) acc[i] *= c;
            for (int kt = 0; kt < 64; kt++) {
                float p = sc[ql_s * SC_STRIDE + kt];
                const float* vrow = &vs[kt * QS_STRIDE + dg];
#pragma unroll
                for (int i = 0; i < 16; i += 4) {
                    float4 vv = *reinterpret_cast<const float4*>(&vrow[i]);
                    acc[i + 0] = fmaf(p, vv.x, acc[i + 0]);
                    acc[i + 1] = fmaf(p, vv.y, acc[i + 1]);
                    acc[i + 2] = fmaf(p, vv.z, acc[i + 2]);
                    acc[i + 3] = fmaf(p, vv.w, acc[i + 3]);
                }
            }
        }
    }
    if (tid < 32) lsm[tid] = l;
    __syncthreads();
    {
        float linv = 1.f / lsm[ql_s];
        int gi = qid_s >> 6, s = qid_s & 63;
        float* orow = out + (((size_t)(b * SEQ + s)) * NQ + (kvh * 4 + gi)) * HDIM + dg;
#pragma unroll
        for (int i = 0; i < 16; i++) orow[i] = acc[i] * linv;
    }
}

// ---------------------------------------------------------------------------
// In-place log_softmax over VOCAB per row
// ---------------------------------------------------------------------------
__global__ void __launch_bounds__(256) logsoftmax_kernel(float* __restrict__ x)
{
    const int row = blockIdx.x;
    const int tid = threadIdx.x;
    float* xr = x + (size_t)row * VOCAB;
    float mv = -INFINITY;
    for (int i = tid; i < VOCAB; i += 256) mv = fmaxf(mv, xr[i]);
    float M = block_max(mv);
    float s = 0.f;
    for (int i = tid; i < VOCAB; i += 256) s += __expf(xr[i] - M);
    float S = block_sum(s);
    float lse = M + logf(S);
    for (int i = tid; i < VOCAB; i += 256) xr[i] = xr[i] - lse;
}

// ---------------------------------------------------------------------------
// Launch
// ---------------------------------------------------------------------------
extern "C" void kernel_launch(void* const* d_in, const int* in_sizes, int n_in,
                              void* d_out, int out_size)
{
    const float* inputs_embeds = (const float*)d_in[0];
    const float* past_kv       = (const float*)d_in[1];
    const float* rope          = (const float*)d_in[2];
    const int*   ctx_len       = (const int*)d_in[3];
    // d_in[4] kvcache_start_index unused by reference
    const int*   last_ids      = (const int*)d_in[5];
    const float* hsi           = (const float*)d_in[6];
    const float* hsd           = (const float*)d_in[7];
    const int*   pos_id        = (const int*)d_in[8];
    // d_in[9] attention_mask: tril causal — computed arithmetically
    const float* W_fc   = (const float*)d_in[10];
    const float* W_q    = (const float*)d_in[11];
    const float* W_k    = (const float*)d_in[12];
    const float* W_v    = (const float*)d_in[13];
    const float* W_o    = (const float*)d_in[14];
    const float* W_gate = (const float*)d_in[15];
    const float* W_up   = (const float*)d_in[16];
    const float* W_down = (const float*)d_in[17];
    const float* W_lm   = (const float*)d_in[18];
    const float* w_hidden = (const float*)d_in[19];
    const float* w_input  = (const float*)d_in[20];
    const float* w_post   = (const float*)d_in[21];
    const float* w_final  = (const float*)d_in[22];

    float* out = (float*)d_out;
    float* out_logits   = out;
    float* out_gathered = out + LOGITS_ELEMS;
    float* out_present  = out + PRESENT_OFF;

    void* p;
    cudaGetSymbolAddress(&p, g_hs);     float* hs    = (float*)p;
    cudaGetSymbolAddress(&p, g_normed); float* nrm   = (float*)p;
    cudaGetSymbolAddress(&p, g_q);      float* qb    = (float*)p;
    cudaGetSymbolAddress(&p, g_k);      float* kb    = (float*)p;
    cudaGetSymbolAddress(&p, g_v);      float* vb    = (float*)p;
    cudaGetSymbolAddress(&p, g_attn);   float* attnb = (float*)p;
    cudaGetSymbolAddress(&p, g_hn);     float* hn    = (float*)p;
    cudaGetSymbolAddress(&p, g_gate);   float* gateb = (float*)p;
    cudaGetSymbolAddress(&p, g_act);    float* actb  = (float*)p;
    cudaGetSymbolAddress(&p, g_fn);     float* fnb   = (float*)p;

    cudaFuncSetAttribute(attn_kernel, cudaFuncAttributeMaxDynamicSharedMemorySize,
                         ATTN_SMEM);

    // 1. hs = draft + hsi @ W_fc        (256 x 2048 x 6144)
    sgemm128<1><<<dim3(16, 2), 256>>>(hsi, W_fc, hs, hsd, ROWS, HIDDEN, 6144);
    // 2. normed = [rms(emb), rms(hs)]
    rms_concat_kernel<<<ROWS, 256>>>(inputs_embeds, hs, w_input, w_hidden, nrm);
    // 3. q/k/v GEMMs (K = 4096)
    sgemm128<0><<<dim3(16, 2), 256>>>(nrm, W_q, qb, nullptr, ROWS, NQ * HDIM, 4096);
    sgemm128<0><<<dim3(4, 2), 256>>>(nrm, W_k, kb, nullptr, ROWS, NKV * HDIM, 4096);
    sgemm128<0><<<dim3(4, 2), 256>>>(nrm, W_v, vb, nullptr, ROWS, NKV * HDIM, 4096);
    // 4. present: copy past, then roped k / v appended
    copy_past_kernel<<<8192, 256>>>(past_kv, out_present);
    rope_store_kernel<<<dim3(256, 24), 64>>>(qb, kb, vb, rope, pos_id, out_present);
    // 5. attention
    attn_kernel<<<128, 256, ATTN_SMEM>>>(qb, out_present, ctx_len, attnb);
    // 6. hs += attn @ W_o
    sgemm128<1><<<dim3(16, 2), 256>>>(attnb, W_o, hs, hs, ROWS, HIDDEN, 2048);
    // 7. MLP
    rms_kernel<<<ROWS, 256>>>(hs, w_post, hn);
    sgemm128<0><<<dim3(64, 2), 256>>>(hn, W_gate, gateb, nullptr, ROWS, INTER, 2048);
    sgemm128<2><<<dim3(64, 2), 256>>>(hn, W_up, actb, gateb, ROWS, INTER, 2048);
    sgemm128<1><<<dim3(16, 2), 256>>>(actb, W_down, hs, hs, ROWS, HIDDEN, 8192);
    // 8. gather + final norm
    gather_rms_kernel<<<ROWS, 256>>>(hs, last_ids, w_final, out_gathered, fnb);
    // 9. LM head + log_softmax (in place in output)
    sgemm128<0><<<dim3(250, 2), 256>>>(fnb, W_lm, out_logits, nullptr, ROWS, VOCAB, 2048);
    logsoftmax_kernel<<<ROWS, 256>>>(out_logits);
}

// round 4
// speedup vs baseline: 2.7717x; 2.7717x over previous
#include <cuda_runtime.h>
#include <cuda_bf16.h>
#include <math.h>
#include <stdint.h>

#define BATCH 4
#define SEQ 64
#define PAST 2048
#define TTOT 2112
#define HIDDEN 2048
#define NQ 16
#define NKV 4
#define HDIM 128
#define INTER 8192
#define VOCAB 32000
#define ROWS 256
#define EPS 1e-6f

#define LOGITS_ELEMS (ROWS * VOCAB)
#define GATHERED_ELEMS (ROWS * HIDDEN)
#define PRESENT_OFF (LOGITS_ELEMS + GATHERED_ELEMS)

// ---------------------------------------------------------------------------
// Scratch (device globals)
// ---------------------------------------------------------------------------
__device__ float g_hs[ROWS * HIDDEN];
__device__ float g_normed[ROWS * 2 * HIDDEN];
__device__ float g_qkv[ROWS * 3072];
__device__ float g_attn[ROWS * NQ * HDIM];
__device__ float g_hn[ROWS * HIDDEN];
__device__ float g_gu[ROWS * 2 * INTER];
__device__ float g_act[ROWS * INTER];
__device__ float g_fn[ROWS * HIDDEN];

// ---------------------------------------------------------------------------
// Helpers
// ---------------------------------------------------------------------------
__device__ __forceinline__ float tf32r(float x) {
    uint32_t r;
    asm("cvt.rna.tf32.f32 %0, %1;" : "=r"(r) : "f"(x));
    return __uint_as_float(r);
}

__device__ __forceinline__ void mma_tf32(float* c, const uint32_t* a, const uint32_t* b) {
    asm volatile(
        "mma.sync.aligned.m16n8k8.row.col.f32.tf32.tf32.f32 "
        "{%0,%1,%2,%3}, {%4,%5,%6,%7}, {%8,%9}, {%0,%1,%2,%3};"
        : "+f"(c[0]), "+f"(c[1]), "+f"(c[2]), "+f"(c[3])
        : "r"(a[0]), "r"(a[1]), "r"(a[2]), "r"(a[3]), "r"(b[0]), "r"(b[1]));
}

__device__ __forceinline__ float block_sum(float v) {
    __shared__ float sh[8];
    __shared__ float total;
    int tid = threadIdx.x;
#pragma unroll
    for (int o = 16; o > 0; o >>= 1) v += __shfl_xor_sync(0xffffffffu, v, o);
    if ((tid & 31) == 0) sh[tid >> 5] = v;
    __syncthreads();
    if (tid == 0) {
        float s = 0.f;
#pragma unroll
        for (int i = 0; i < 8; i++) s += sh[i];
        total = s;
    }
    __syncthreads();
    float r = total;
    __syncthreads();
    return r;
}
__device__ __forceinline__ float block_max(float v) {
    __shared__ float sh[8];
    __shared__ float total;
    int tid = threadIdx.x;
#pragma unroll
    for (int o = 16; o > 0; o >>= 1) v = fmaxf(v, __shfl_xor_sync(0xffffffffu, v, o));
    if ((tid & 31) == 0) sh[tid >> 5] = v;
    __syncthreads();
    if (tid == 0) {
        float s = -INFINITY;
#pragma unroll
        for (int i = 0; i < 8; i++) s = fmaxf(s, sh[i]);
        total = s;
    }
    __syncthreads();
    float r = total;
    __syncthreads();
    return r;
}

// ---------------------------------------------------------------------------
// Tensor-core tf32 GEMM core.  C[M=256, :] tile 128x128, 256 threads.
// A [256,K] row-major. B [K,ldB], cols nB..nB+127. C stride ldC, cols nC..
// EPI 0: C = acc ; EPI 1: C = acc + Aux (Aux stride ldC, may alias C)
// Dynamic smem: As 2x[128][36], Bs 2x[32][136]  = 71680 B
// ---------------------------------------------------------------------------
#define GSMEM 71680

template <int EPI>
__device__ __forceinline__ void gemm_core(
    const float* __restrict__ A, const float* __restrict__ B,
    float* __restrict__ C, const float* __restrict__ Aux,
    int K, int ldB, int nB, int ldC, int nC)
{
    extern __shared__ float sm[];
    float* AsBuf[2] = { sm, sm + 4608 };
    float* BsBuf[2] = { sm + 9216, sm + 13568 };

    const int tid = threadIdx.x;
    const int lane = tid & 31;
    const int wid = tid >> 5;
    const int warpM = wid & 1;
    const int warpN = wid >> 1;
    const int gid = lane >> 2;
    const int tig = lane & 3;
    const int mBase = blockIdx.y * 128;

    int aRow[4], aCol[4], bRow[4], bCol[4];
#pragma unroll
    for (int i = 0; i < 4; i++) {
        int fi = tid + 256 * i;
        aRow[i] = fi >> 3;  aCol[i] = (fi & 7) << 2;
        bRow[i] = fi >> 5;  bCol[i] = (fi & 31) << 2;
    }

    float4 aReg[4], bReg[4];
#pragma unroll
    for (int i = 0; i < 4; i++) {
        aReg[i] = *reinterpret_cast<const float4*>(A + (size_t)(mBase + aRow[i]) * K + aCol[i]);
        bReg[i] = *reinterpret_cast<const float4*>(B + (size_t)bRow[i] * ldB + nB + bCol[i]);
    }

    float acc[4][4][4];
#pragma unroll
    for (int a = 0; a < 4; a++)
#pragma unroll
        for (int b = 0; b < 4; b++)
#pragma unroll
            for (int c = 0; c < 4; c++) acc[a][b][c] = 0.f;

    // store prologue into buf 0
    {
        float* Ad = AsBuf[0]; float* Bd = BsBuf[0];
#pragma unroll
        for (int i = 0; i < 4; i++) {
            float4 v = aReg[i];
            v.x = tf32r(v.x); v.y = tf32r(v.y); v.z = tf32r(v.z); v.w = tf32r(v.w);
            *reinterpret_cast<float4*>(Ad + aRow[i] * 36 + aCol[i]) = v;
            float4 w = bReg[i];
            w.x = tf32r(w.x); w.y = tf32r(w.y); w.z = tf32r(w.z); w.w = tf32r(w.w);
            *reinterpret_cast<float4*>(Bd + bRow[i] * 136 + bCol[i]) = w;
        }
    }
    __syncthreads();

    int buf = 0;
    for (int k0 = 0; k0 < K; k0 += 32) {
        const bool more = (k0 + 32) < K;
        if (more) {
#pragma unroll
            for (int i = 0; i < 4; i++) {
                aReg[i] = *reinterpret_cast<const float4*>(
                    A + (size_t)(mBase + aRow[i]) * K + k0 + 32 + aCol[i]);
                bReg[i] = *reinterpret_cast<const float4*>(
                    B + (size_t)(k0 + 32 + bRow[i]) * ldB + nB + bCol[i]);
            }
        }
        const float* AsR = AsBuf[buf];
        const float* BsR = BsBuf[buf];
#pragma unroll
        for (int ks = 0; ks < 32; ks += 8) {
            uint32_t af[4][4];
#pragma unroll
            for (int mi = 0; mi < 4; mi++) {
                int r0 = (warpM * 64 + mi * 16 + gid) * 36;
                af[mi][0] = __float_as_uint(AsR[r0 + ks + tig]);
                af[mi][1] = __float_as_uint(AsR[r0 + 288 + ks + tig]);
                af[mi][2] = __float_as_uint(AsR[r0 + ks + 4 + tig]);
                af[mi][3] = __float_as_uint(AsR[r0 + 288 + ks + 4 + tig]);
            }
            uint32_t bf[4][2];
#pragma unroll
            for (int nj = 0; nj < 4; nj++) {
                int c0 = warpN * 32 + nj * 8 + gid;
                bf[nj][0] = __float_as_uint(BsR[(ks + tig) * 136 + c0]);
                bf[nj][1] = __float_as_uint(BsR[(ks + 4 + tig) * 136 + c0]);
            }
#pragma unroll
            for (int mi = 0; mi < 4; mi++)
#pragma unroll
                for (int nj = 0; nj < 4; nj++)
                    mma_tf32(acc[mi][nj], af[mi], bf[nj]);
        }
        if (more) {
            float* Ad = AsBuf[buf ^ 1]; float* Bd = BsBuf[buf ^ 1];
#pragma unroll
            for (int i = 0; i < 4; i++) {
                float4 v = aReg[i];
                v.x = tf32r(v.x); v.y = tf32r(v.y); v.z = tf32r(v.z); v.w = tf32r(v.w);
                *reinterpret_cast<float4*>(Ad + aRow[i] * 36 + aCol[i]) = v;
                float4 w = bReg[i];
                w.x = tf32r(w.x); w.y = tf32r(w.y); w.z = tf32r(w.z); w.w = tf32r(w.w);
                *reinterpret_cast<float4*>(Bd + bRow[i] * 136 + bCol[i]) = w;
            }
        }
        __syncthreads();
        buf ^= 1;
    }

#pragma unroll
    for (int mi = 0; mi < 4; mi++) {
        int row = mBase + warpM * 64 + mi * 16 + gid;
#pragma unroll
        for (int nj = 0; nj < 4; nj++) {
            int col = nC + warpN * 32 + nj * 8 + tig * 2;
            float2 v0 = make_float2(acc[mi][nj][0], acc[mi][nj][1]);
            float2 v1 = make_float2(acc[mi][nj][2], acc[mi][nj][3]);
            size_t o0 = (size_t)row * ldC + col;
            size_t o1 = (size_t)(row + 8) * ldC + col;
            if (EPI == 1) {
                float2 x0 = *reinterpret_cast<const float2*>(Aux + o0);
                float2 x1 = *reinterpret_cast<const float2*>(Aux + o1);
                v0.x += x0.x; v0.y += x0.y;
                v1.x += x1.x; v1.y += x1.y;
            }
            *reinterpret_cast<float2*>(C + o0) = v0;
            *reinterpret_cast<float2*>(C + o1) = v1;
        }
    }
}

template <int EPI>
__global__ void __launch_bounds__(256) tgemm(
    const float* __restrict__ A, const float* __restrict__ B,
    float* __restrict__ C, const float* __restrict__ Aux, int K, int ldB, int ldC)
{
    gemm_core<EPI>(A, B, C, Aux, K, ldB, blockIdx.x * 128, ldC, blockIdx.x * 128);
}

// fused q/k/v: grid (24, 2); bx<16 -> Wq(N=2048), 16..19 -> Wk(512), 20..23 -> Wv(512)
__global__ void __launch_bounds__(256) tgemm_qkv(
    const float* __restrict__ A, const float* __restrict__ Bq,
    const float* __restrict__ Bk, const float* __restrict__ Bv, float* __restrict__ C)
{
    int bx = blockIdx.x;
    const float* B; int ldB, nB;
    if (bx < 16)      { B = Bq; ldB = 2048; nB = bx * 128; }
    else if (bx < 20) { B = Bk; ldB = 512;  nB = (bx - 16) * 128; }
    else              { B = Bv; ldB = 512;  nB = (bx - 20) * 128; }
    gemm_core<0>(A, B, C, nullptr, 4096, ldB, nB, 3072, bx * 128);
}

// fused gate|up: grid (128, 2); bx<64 -> gate, else up. C = g_gu [256][16384]
__global__ void __launch_bounds__(256) tgemm_gu(
    const float* __restrict__ A, const float* __restrict__ Bg,
    const float* __restrict__ Bu, float* __restrict__ C)
{
    int bx = blockIdx.x;
    const float* B = (bx < 64) ? Bg : Bu;
    int nB = (bx & 63) * 128;
    gemm_core<0>(A, B, C, nullptr, 2048, INTER, nB, 2 * INTER, bx * 128);
}

// act[r][c] = silu(gu[r][c]) * gu[r][c+8192]
__global__ void __launch_bounds__(256) silu_mul_kernel(
    const float* __restrict__ gu, float* __restrict__ act)
{
    int i = blockIdx.x * 256 + threadIdx.x;
    int r = i >> 13, c = i & 8191;
    float g = gu[(size_t)r * (2 * INTER) + c];
    float u = gu[(size_t)r * (2 * INTER) + INTER + c];
    act[i] = (g / (1.f + expf(-g))) * u;
}

// ---------------------------------------------------------------------------
// Norm / copy / rope / gather / logsoftmax
// ---------------------------------------------------------------------------
__global__ void __launch_bounds__(256) rms_concat_kernel(
    const float* __restrict__ emb, const float* __restrict__ hs,
    const float* __restrict__ w_in, const float* __restrict__ w_hid,
    float* __restrict__ normed)
{
    const int row = blockIdx.x;
    const int tid = threadIdx.x;
    const float* x1 = emb + (size_t)row * HIDDEN;
    const float* x2 = hs + (size_t)row * HIDDEN;
    float s1 = 0.f, s2 = 0.f;
    for (int i = tid; i < HIDDEN; i += 256) {
        float a = x1[i]; s1 += a * a;
        float b = x2[i]; s2 += b * b;
    }
    float r1 = block_sum(s1);
    float r2 = block_sum(s2);
    float inv1 = rsqrtf(r1 / (float)HIDDEN + EPS);
    float inv2 = rsqrtf(r2 / (float)HIDDEN + EPS);
    float* o = normed + (size_t)row * (2 * HIDDEN);
    for (int i = tid; i < HIDDEN; i += 256) {
        o[i]          = x1[i] * inv1 * w_in[i];
        o[HIDDEN + i] = x2[i] * inv2 * w_hid[i];
    }
}

__global__ void __launch_bounds__(256) rms_kernel(
    const float* __restrict__ x, const float* __restrict__ w, float* __restrict__ y)
{
    const int row = blockIdx.x;
    const int tid = threadIdx.x;
    const float* xr = x + (size_t)row * HIDDEN;
    float s = 0.f;
    for (int i = tid; i < HIDDEN; i += 256) { float a = xr[i]; s += a * a; }
    float r = block_sum(s);
    float inv = rsqrtf(r / (float)HIDDEN + EPS);
    float* yr = y + (size_t)row * HIDDEN;
    for (int i = tid; i < HIDDEN; i += 256) yr[i] = xr[i] * inv * w[i];
}

__global__ void __launch_bounds__(256) gather_rms_kernel(
    const float* __restrict__ hs, const int* __restrict__ lt,
    const float* __restrict__ w, float* __restrict__ out_gathered,
    float* __restrict__ fn)
{
    const int row = blockIdx.x;
    const int tid = threadIdx.x;
    const int b = row >> 6;
    const int src_s = lt[row];
    const float* x = hs + ((size_t)b * SEQ + src_s) * HIDDEN;
    float s = 0.f;
    for (int i = tid; i < HIDDEN; i += 256) { float a = x[i]; s += a * a; }
    float r = block_sum(s);
    float inv = rsqrtf(r / (float)HIDDEN + EPS);
    float* og = out_gathered + (size_t)row * HIDDEN;
    float* fr = fn + (size_t)row * HIDDEN;
    for (int i = tid; i < HIDDEN; i += 256) {
        float a = x[i];
        og[i] = a;
        fr[i] = a * inv * w[i];
    }
}

__global__ void __launch_bounds__(256) copy_past_kernel(
    const float* __restrict__ past, float* __restrict__ present)
{
    const int idx = blockIdx.x * 256 + threadIdx.x;  // 2,097,152 float4
    const int lane = idx & 31;
    const int row = idx >> 5;
    const int t = row & 2047;
    const int bch = row >> 11;
    const float4* src = reinterpret_cast<const float4*>(past) + idx;
    float4* dst = reinterpret_cast<float4*>(present) + ((size_t)bch * TTOT + t) * 32 + lane;
    *dst = *src;
}

// q in place (inside g_qkv), roped k -> present, v -> present. grid (256,24) blk 64
__global__ void __launch_bounds__(64) rope_store_kernel(
    float* __restrict__ qkv, const float* __restrict__ rope,
    const int* __restrict__ pos_ids, float* __restrict__ present)
{
    const int bs = blockIdx.x;
    const int h = blockIdx.y;
    const int d = threadIdx.x;
    const int b = bs >> 6, s = bs & 63;
    const int pos = pos_ids[bs];
    const float c = rope[(size_t)pos * 128 + d];
    const float sn = rope[(size_t)pos * 128 + 64 + d];
    float* row = qkv + (size_t)bs * 3072;
    if (h < 16) {
        float* base = row + h * 128;
        float x1 = base[d], x2 = base[d + 64];
        base[d] = x1 * c - x2 * sn;
        base[d + 64] = x2 * c + x1 * sn;
    } else if (h < 20) {
        const int kh = h - 16;
        const float* base = row + 2048 + kh * 128;
        float x1 = base[d], x2 = base[d + 64];
        float* dst = present + (((size_t)(b * 2 + 0) * NKV + kh) * TTOT + PAST + s) * HDIM;
        dst[d] = x1 * c - x2 * sn;
        dst[d + 64] = x2 * c + x1 * sn;
    } else {
        const int vh = h - 20;
        const float* base = row + 2560 + vh * 128;
        float* dst = present + (((size_t)(b * 2 + 1) * NKV + vh) * TTOT + PAST + s) * HDIM;
        dst[d] = base[d];
        dst[d + 64] = base[d + 64];
    }
}

// ---------------------------------------------------------------------------
// Attention (fp32, unchanged logic; q read from g_qkv stride 3072)
// ---------------------------------------------------------------------------
#define QS_STRIDE 132
#define SC_STRIDE 65
#define ATTN_SMEM ((32 * QS_STRIDE + 64 * QS_STRIDE + 64 * QS_STRIDE + 32 * SC_STRIDE + 64) * 4)

__global__ void __launch_bounds__(256) attn_kernel(
    const float* __restrict__ qkv, const float* __restrict__ kv,
    const int* __restrict__ ctx_len, float* __restrict__ out)
{
    extern __shared__ float sm[];
    float* qs = sm;
    float* ks = qs + 32 * QS_STRIDE;
    float* vs = ks + 64 * QS_STRIDE;
    float* sc = vs + 64 * QS_STRIDE;
    float* corr = sc + 32 * SC_STRIDE;
    float* lsm = corr + 32;

    const int tid = threadIdx.x;
    const int blk = blockIdx.x;
    const int qb = blk & 7;
    const int kvh = (blk >> 3) & 3;
    const int b = blk >> 5;

    for (int i = tid; i < 32 * 128; i += 256) {
        int ql = i >> 7, d = i & 127;
        int qid = qb * 32 + ql;
        int gi = qid >> 6, s = qid & 63;
        qs[ql * QS_STRIDE + d] =
            qkv[(size_t)(b * SEQ + s) * 3072 + (kvh * 4 + gi) * 128 + d];
    }

    float acc[16];
#pragma unroll
    for (int i = 0; i < 16; i++) acc[i] = 0.f;
    float m = -INFINITY, l = 0.f;

    const float* Kb = kv + (((size_t)(b * 2 + 0)) * NKV + kvh) * TTOT * HDIM;
    const float* Vb = kv + (((size_t)(b * 2 + 1)) * NKV + kvh) * TTOT * HDIM;
    const int ctx = ctx_len[b];

    const int ql_s = tid >> 3;
    const int ktg = tid & 7;
    const int qid_s = qb * 32 + ql_s;
    const int s_q = qid_s & 63;
    const int dg = (tid & 7) * 16;

    for (int t0 = 0; t0 < TTOT; t0 += 64) {
        __syncthreads();
        for (int i = tid * 4; i < 64 * 128; i += 1024) {
            int r = i >> 7, d = i & 127;
            *reinterpret_cast<float4*>(&ks[r * QS_STRIDE + d]) =
                *reinterpret_cast<const float4*>(&Kb[(size_t)(t0 + r) * HDIM + d]);
            *reinterpret_cast<float4*>(&vs[r * QS_STRIDE + d]) =
                *reinterpret_cast<const float4*>(&Vb[(size_t)(t0 + r) * HDIM + d]);
        }
        __syncthreads();
        {
            const float* qrow = &qs[ql_s * QS_STRIDE];
#pragma unroll
            for (int j = 0; j < 8; j++) {
                int kt = ktg + 8 * j;
                const float* krow = &ks[kt * QS_STRIDE];
                float dot = 0.f;
#pragma unroll
                for (int d = 0; d < 128; d += 4) {
                    float4 qv = *reinterpret_cast<const float4*>(&qrow[d]);
                    float4 kk = *reinterpret_cast<const float4*>(&krow[d]);
                    dot = fmaf(qv.x, kk.x, dot);
                    dot = fmaf(qv.y, kk.y, dot);
                    dot = fmaf(qv.z, kk.z, dot);
                    dot = fmaf(qv.w, kk.w, dot);
                }
                int t = t0 + kt;
                bool valid = (t < PAST) ? (t < ctx) : ((t - PAST) <= s_q);
                sc[ql_s * SC_STRIDE + kt] =
                    valid ? dot * 0.08838834764831845f : -INFINITY;
            }
        }
        __syncthreads();
        if (tid < 32) {
            float mt = -INFINITY;
#pragma unroll 8
            for (int j = 0; j < 64; j++) mt = fmaxf(mt, sc[tid * SC_STRIDE + j]);
            float mnew = fmaxf(m, mt);
            float c, sum = 0.f;
            if (mnew == -INFINITY) {
                c = 1.f;
                for (int j = 0; j < 64; j++) sc[tid * SC_STRIDE + j] = 0.f;
            } else {
                c = __expf(m - mnew);
#pragma unroll 8
                for (int j = 0; j < 64; j++) {
                    float p = __expf(sc[tid * SC_STRIDE + j] - mnew);
                    sc[tid * SC_STRIDE + j] = p;
                    sum += p;
                }
            }
            l = l * c + sum;
            m = mnew;
            corr[tid] = c;
        }
        __syncthreads();
        {
            float c = corr[ql_s];
#pragma unroll
            for (int i = 0; i < 16; i++) acc[i] *= c;
            for (int kt = 0; kt < 64; kt++) {
                float p = sc[ql_s * SC_STRIDE + kt];
                const float* vrow = &vs[kt * QS_STRIDE + dg];
#pragma unroll
                for (int i = 0; i < 16; i += 4) {
                    float4 vv = *reinterpret_cast<const float4*>(&vrow[i]);
                    acc[i + 0] = fmaf(p, vv.x, acc[i + 0]);
                    acc[i + 1] = fmaf(p, vv.y, acc[i + 1]);
                    acc[i + 2] = fmaf(p, vv.z, acc[i + 2]);
                    acc[i + 3] = fmaf(p, vv.w, acc[i + 3]);
                }
            }
        }
    }
    if (tid < 32) lsm[tid] = l;
    __syncthreads();
    {
        float linv = 1.f / lsm[ql_s];
        int gi = qid_s >> 6, s = qid_s & 63;
        float* orow = out + (((size_t)(b * SEQ + s)) * NQ + (kvh * 4 + gi)) * HDIM + dg;
#pragma unroll
        for (int i = 0; i < 16; i++) orow[i] = acc[i] * linv;
    }
}

__global__ void __launch_bounds__(256) logsoftmax_kernel(float* __restrict__ x)
{
    const int row = blockIdx.x;
    const int tid = threadIdx.x;
    float* xr = x + (size_t)row * VOCAB;
    float mv = -INFINITY;
    for (int i = tid; i < VOCAB; i += 256) mv = fmaxf(mv, xr[i]);
    float M = block_max(mv);
    float s = 0.f;
    for (int i = tid; i < VOCAB; i += 256) s += __expf(xr[i] - M);
    float S = block_sum(s);
    float lse = M + logf(S);
    for (int i = tid; i < VOCAB; i += 256) xr[i] = xr[i] - lse;
}

// ---------------------------------------------------------------------------
// Launch
// ---------------------------------------------------------------------------
extern "C" void kernel_launch(void* const* d_in, const int* in_sizes, int n_in,
                              void* d_out, int out_size)
{
    const float* inputs_embeds = (const float*)d_in[0];
    const float* past_kv       = (const float*)d_in[1];
    const float* rope          = (const float*)d_in[2];
    const int*   ctx_len       = (const int*)d_in[3];
    const int*   last_ids      = (const int*)d_in[5];
    const float* hsi           = (const float*)d_in[6];
    const float* hsd           = (const float*)d_in[7];
    const int*   pos_id        = (const int*)d_in[8];
    const float* W_fc   = (const float*)d_in[10];
    const float* W_q    = (const float*)d_in[11];
    const float* W_k    = (const float*)d_in[12];
    const float* W_v    = (const float*)d_in[13];
    const float* W_o    = (const float*)d_in[14];
    const float* W_gate = (const float*)d_in[15];
    const float* W_up   = (const float*)d_in[16];
    const float* W_down = (const float*)d_in[17];
    const float* W_lm   = (const float*)d_in[18];
    const float* w_hidden = (const float*)d_in[19];
    const float* w_input  = (const float*)d_in[20];
    const float* w_post   = (const float*)d_in[21];
    const float* w_final  = (const float*)d_in[22];

    float* out = (float*)d_out;
    float* out_logits   = out;
    float* out_gathered = out + LOGITS_ELEMS;
    float* out_present  = out + PRESENT_OFF;

    void* p;
    cudaGetSymbolAddress(&p, g_hs);     float* hs   = (float*)p;
    cudaGetSymbolAddress(&p, g_normed); float* nrm  = (float*)p;
    cudaGetSymbolAddress(&p, g_qkv);    float* qkv  = (float*)p;
    cudaGetSymbolAddress(&p, g_attn);   float* attnb= (float*)p;
    cudaGetSymbolAddress(&p, g_hn);     float* hn   = (float*)p;
    cudaGetSymbolAddress(&p, g_gu);     float* gu   = (float*)p;
    cudaGetSymbolAddress(&p, g_act);    float* actb = (float*)p;
    cudaGetSymbolAddress(&p, g_fn);     float* fnb  = (float*)p;

    cudaFuncSetAttribute(attn_kernel, cudaFuncAttributeMaxDynamicSharedMemorySize, ATTN_SMEM);
    cudaFuncSetAttribute(tgemm<0>, cudaFuncAttributeMaxDynamicSharedMemorySize, GSMEM);
    cudaFuncSetAttribute(tgemm<1>, cudaFuncAttributeMaxDynamicSharedMemorySize, GSMEM);
    cudaFuncSetAttribute(tgemm_qkv, cudaFuncAttributeMaxDynamicSharedMemorySize, GSMEM);
    cudaFuncSetAttribute(tgemm_gu, cudaFuncAttributeMaxDynamicSharedMemorySize, GSMEM);

    // 1. hs = draft + hsi @ W_fc
    tgemm<1><<<dim3(16, 2), 256, GSMEM>>>(hsi, W_fc, hs, hsd, 6144, HIDDEN, HIDDEN);
    // 2. normed = [rms(emb), rms(hs)]
    rms_concat_kernel<<<ROWS, 256>>>(inputs_embeds, hs, w_input, w_hidden, nrm);
    // 3. fused qkv
    tgemm_qkv<<<dim3(24, 2), 256, GSMEM>>>(nrm, W_q, W_k, W_v, qkv);
    // 4. present
    copy_past_kernel<<<8192, 256>>>(past_kv, out_present);
    rope_store_kernel<<<dim3(256, 24), 64>>>(qkv, rope, pos_id, out_present);
    // 5. attention
    attn_kernel<<<128, 256, ATTN_SMEM>>>(qkv, out_present, ctx_len, attnb);
    // 6. hs += attn @ W_o
    tgemm<1><<<dim3(16, 2), 256, GSMEM>>>(attnb, W_o, hs, hs, 2048, HIDDEN, HIDDEN);
    // 7. MLP
    rms_kernel<<<ROWS, 256>>>(hs, w_post, hn);
    tgemm_gu<<<dim3(128, 2), 256, GSMEM>>>(hn, W_gate, W_up, gu);
    silu_mul_kernel<<<8192, 256>>>(gu, actb);
    tgemm<1><<<dim3(16, 2), 256, GSMEM>>>(actb, W_down, hs, hs, INTER, HIDDEN, HIDDEN);
    // 8. gather + final norm
    gather_rms_kernel<<<ROWS, 256>>>(hs, last_ids, w_final, out_gathered, fnb);
    // 9. LM head + log_softmax
    tgemm<0><<<dim3(250, 2), 256, GSMEM>>>(fnb, W_lm, out_logits, nullptr, 2048, VOCAB, VOCAB);
    logsoftmax_kernel<<<ROWS, 256>>>(out_logits);
}

// round 5
// speedup vs baseline: 4.0988x; 1.4788x over previous
#include <cuda_runtime.h>
#include <cuda_bf16.h>
#include <math.h>
#include <stdint.h>

#define BATCH 4
#define SEQ 64
#define PAST 2048
#define TTOT 2112
#define HIDDEN 2048
#define NQ 16
#define NKV 4
#define HDIM 128
#define INTER 8192
#define VOCAB 32000
#define ROWS 256
#define EPS 1e-6f

#define LOGITS_ELEMS (ROWS * VOCAB)
#define GATHERED_ELEMS (ROWS * HIDDEN)
#define PRESENT_OFF (LOGITS_ELEMS + GATHERED_ELEMS)

// ---------------------------------------------------------------------------
// Scratch (device globals)
// ---------------------------------------------------------------------------
__device__ float g_hs[ROWS * HIDDEN];
__device__ float g_normed[ROWS * 2 * HIDDEN];
__device__ float g_qkv[ROWS * 3072];
__device__ float g_attn[ROWS * NQ * HDIM];
__device__ float g_hn[ROWS * HIDDEN];
__device__ float g_gu[ROWS * 2 * INTER];
__device__ float g_act[ROWS * INTER];
__device__ float g_fn[ROWS * HIDDEN];
__device__ float g_part[4 * ROWS * 3072];   // split-K partials (max N=3072, S=4)

// ---------------------------------------------------------------------------
// Helpers
// ---------------------------------------------------------------------------
__device__ __forceinline__ float tf32r(float x) {
    uint32_t r;
    asm("cvt.rna.tf32.f32 %0, %1;" : "=r"(r) : "f"(x));
    return __uint_as_float(r);
}

__device__ __forceinline__ void mma_tf32(float* c, const uint32_t* a, const uint32_t* b) {
    asm volatile(
        "mma.sync.aligned.m16n8k8.row.col.f32.tf32.tf32.f32 "
        "{%0,%1,%2,%3}, {%4,%5,%6,%7}, {%8,%9}, {%0,%1,%2,%3};"
        : "+f"(c[0]), "+f"(c[1]), "+f"(c[2]), "+f"(c[3])
        : "r"(a[0]), "r"(a[1]), "r"(a[2]), "r"(a[3]), "r"(b[0]), "r"(b[1]));
}

__device__ __forceinline__ float block_sum(float v) {
    __shared__ float sh[8];
    __shared__ float total;
    int tid = threadIdx.x;
#pragma unroll
    for (int o = 16; o > 0; o >>= 1) v += __shfl_xor_sync(0xffffffffu, v, o);
    if ((tid & 31) == 0) sh[tid >> 5] = v;
    __syncthreads();
    if (tid == 0) {
        float s = 0.f;
#pragma unroll
        for (int i = 0; i < 8; i++) s += sh[i];
        total = s;
    }
    __syncthreads();
    float r = total;
    __syncthreads();
    return r;
}
__device__ __forceinline__ float block_max(float v) {
    __shared__ float sh[8];
    __shared__ float total;
    int tid = threadIdx.x;
#pragma unroll
    for (int o = 16; o > 0; o >>= 1) v = fmaxf(v, __shfl_xor_sync(0xffffffffu, v, o));
    if ((tid & 31) == 0) sh[tid >> 5] = v;
    __syncthreads();
    if (tid == 0) {
        float s = -INFINITY;
#pragma unroll
        for (int i = 0; i < 8; i++) s = fmaxf(s, sh[i]);
        total = s;
    }
    __syncthreads();
    float r = total;
    __syncthreads();
    return r;
}

// ---------------------------------------------------------------------------
// Tensor-core tf32 GEMM core.  128x128 C tile, 256 threads, double-buffered.
// A: row-major, leading dim lda, pre-offset to k-start. kLen multiple of 32.
// B: [kLen rows, ldB], cols nB.. ; pre-offset to k-start row.
// EPI 0: C = acc ; EPI 1: C = acc + Aux
// Dynamic smem: 2x A[128][36] + 2x B[32][136] = 71680 B
// ---------------------------------------------------------------------------
#define GSMEM 71680

template <int EPI>
__device__ __forceinline__ void gemm_core(
    const float* __restrict__ A, int lda,
    const float* __restrict__ B,
    float* __restrict__ C, const float* __restrict__ Aux,
    int kLen, int ldB, int nB, int ldC, int nC)
{
    extern __shared__ float sm[];
    float* AsBuf[2] = { sm, sm + 4608 };
    float* BsBuf[2] = { sm + 9216, sm + 13568 };

    const int tid = threadIdx.x;
    const int lane = tid & 31;
    const int wid = tid >> 5;
    const int warpM = wid & 1;
    const int warpN = wid >> 1;
    const int gid = lane >> 2;
    const int tig = lane & 3;
    const int mBase = blockIdx.y * 128;

    int aRow[4], aCol[4], bRow[4], bCol[4];
#pragma unroll
    for (int i = 0; i < 4; i++) {
        int fi = tid + 256 * i;
        aRow[i] = fi >> 3;  aCol[i] = (fi & 7) << 2;
        bRow[i] = fi >> 5;  bCol[i] = (fi & 31) << 2;
    }

    float4 aReg[4], bReg[4];
#pragma unroll
    for (int i = 0; i < 4; i++) {
        aReg[i] = *reinterpret_cast<const float4*>(A + (size_t)(mBase + aRow[i]) * lda + aCol[i]);
        bReg[i] = *reinterpret_cast<const float4*>(B + (size_t)bRow[i] * ldB + nB + bCol[i]);
    }

    float acc[4][4][4];
#pragma unroll
    for (int a = 0; a < 4; a++)
#pragma unroll
        for (int b = 0; b < 4; b++)
#pragma unroll
            for (int c = 0; c < 4; c++) acc[a][b][c] = 0.f;

    {
        float* Ad = AsBuf[0]; float* Bd = BsBuf[0];
#pragma unroll
        for (int i = 0; i < 4; i++) {
            float4 v = aReg[i];
            v.x = tf32r(v.x); v.y = tf32r(v.y); v.z = tf32r(v.z); v.w = tf32r(v.w);
            *reinterpret_cast<float4*>(Ad + aRow[i] * 36 + aCol[i]) = v;
            float4 w = bReg[i];
            w.x = tf32r(w.x); w.y = tf32r(w.y); w.z = tf32r(w.z); w.w = tf32r(w.w);
            *reinterpret_cast<float4*>(Bd + bRow[i] * 136 + bCol[i]) = w;
        }
    }
    __syncthreads();

    int buf = 0;
    for (int k0 = 0; k0 < kLen; k0 += 32) {
        const bool more = (k0 + 32) < kLen;
        if (more) {
#pragma unroll
            for (int i = 0; i < 4; i++) {
                aReg[i] = *reinterpret_cast<const float4*>(
                    A + (size_t)(mBase + aRow[i]) * lda + k0 + 32 + aCol[i]);
                bReg[i] = *reinterpret_cast<const float4*>(
                    B + (size_t)(k0 + 32 + bRow[i]) * ldB + nB + bCol[i]);
            }
        }
        const float* AsR = AsBuf[buf];
        const float* BsR = BsBuf[buf];
#pragma unroll
        for (int ks = 0; ks < 32; ks += 8) {
            uint32_t af[4][4];
#pragma unroll
            for (int mi = 0; mi < 4; mi++) {
                int r0 = (warpM * 64 + mi * 16 + gid) * 36;
                af[mi][0] = __float_as_uint(AsR[r0 + ks + tig]);
                af[mi][1] = __float_as_uint(AsR[r0 + 288 + ks + tig]);
                af[mi][2] = __float_as_uint(AsR[r0 + ks + 4 + tig]);
                af[mi][3] = __float_as_uint(AsR[r0 + 288 + ks + 4 + tig]);
            }
            uint32_t bf[4][2];
#pragma unroll
            for (int nj = 0; nj < 4; nj++) {
                int c0 = warpN * 32 + nj * 8 + gid;
                bf[nj][0] = __float_as_uint(BsR[(ks + tig) * 136 + c0]);
                bf[nj][1] = __float_as_uint(BsR[(ks + 4 + tig) * 136 + c0]);
            }
#pragma unroll
            for (int mi = 0; mi < 4; mi++)
#pragma unroll
                for (int nj = 0; nj < 4; nj++)
                    mma_tf32(acc[mi][nj], af[mi], bf[nj]);
        }
        if (more) {
            float* Ad = AsBuf[buf ^ 1]; float* Bd = BsBuf[buf ^ 1];
#pragma unroll
            for (int i = 0; i < 4; i++) {
                float4 v = aReg[i];
                v.x = tf32r(v.x); v.y = tf32r(v.y); v.z = tf32r(v.z); v.w = tf32r(v.w);
                *reinterpret_cast<float4*>(Ad + aRow[i] * 36 + aCol[i]) = v;
                float4 w = bReg[i];
                w.x = tf32r(w.x); w.y = tf32r(w.y); w.z = tf32r(w.z); w.w = tf32r(w.w);
                *reinterpret_cast<float4*>(Bd + bRow[i] * 136 + bCol[i]) = w;
            }
        }
        __syncthreads();
        buf ^= 1;
    }

#pragma unroll
    for (int mi = 0; mi < 4; mi++) {
        int row = blockIdx.y * 128 + warpM * 64 + mi * 16 + gid;
#pragma unroll
        for (int nj = 0; nj < 4; nj++) {
            int col = nC + warpN * 32 + nj * 8 + tig * 2;
            float2 v0 = make_float2(acc[mi][nj][0], acc[mi][nj][1]);
            float2 v1 = make_float2(acc[mi][nj][2], acc[mi][nj][3]);
            size_t o0 = (size_t)row * ldC + col;
            size_t o1 = (size_t)(row + 8) * ldC + col;
            if (EPI == 1) {
                float2 x0 = *reinterpret_cast<const float2*>(Aux + o0);
                float2 x1 = *reinterpret_cast<const float2*>(Aux + o1);
                v0.x += x0.x; v0.y += x0.y;
                v1.x += x1.x; v1.y += x1.y;
            }
            *reinterpret_cast<float2*>(C + o0) = v0;
            *reinterpret_cast<float2*>(C + o1) = v1;
        }
    }
}

// Unsplit GEMM (gu select / lm)
template <int EPI>
__global__ void __launch_bounds__(256) tgemm(
    const float* __restrict__ A, const float* __restrict__ B,
    float* __restrict__ C, const float* __restrict__ Aux, int K, int ldB, int ldC)
{
    gemm_core<EPI>(A, K, B, C, Aux, K, ldB, blockIdx.x * 128, ldC, blockIdx.x * 128);
}

// Split-K GEMM: grid (N/128, 2, S). Partial z -> P + z*ROWS*ldC.
__global__ void __launch_bounds__(256) tgemm_split(
    const float* __restrict__ A, int lda, const float* __restrict__ B,
    float* __restrict__ P, int kLen, int ldB, int ldC)
{
    int z = blockIdx.z;
    gemm_core<0>(A + (size_t)z * kLen, lda,
                 B + (size_t)z * kLen * ldB,
                 P + (size_t)z * ROWS * ldC, nullptr,
                 kLen, ldB, blockIdx.x * 128, ldC, blockIdx.x * 128);
}

// Split-K fused q/k/v: grid (24, 2, 4). K=4096, kLen=1024, out ldC 3072.
__global__ void __launch_bounds__(256) tgemm_qkv_split(
    const float* __restrict__ A, const float* __restrict__ Bq,
    const float* __restrict__ Bk, const float* __restrict__ Bv, float* __restrict__ P)
{
    int bx = blockIdx.x, z = blockIdx.z;
    const float* B; int ldB, nB;
    if (bx < 16)      { B = Bq; ldB = 2048; nB = bx * 128; }
    else if (bx < 20) { B = Bk; ldB = 512;  nB = (bx - 16) * 128; }
    else              { B = Bv; ldB = 512;  nB = (bx - 20) * 128; }
    gemm_core<0>(A + (size_t)z * 1024, 4096,
                 B + (size_t)z * 1024 * ldB,
                 P + (size_t)z * ROWS * 3072, nullptr,
                 1024, ldB, nB, 3072, bx * 128);
}

// Fused gate|up (unsplit, 256 blocks): grid (128, 2)
__global__ void __launch_bounds__(256) tgemm_gu(
    const float* __restrict__ A, const float* __restrict__ Bg,
    const float* __restrict__ Bu, float* __restrict__ C)
{
    int bx = blockIdx.x;
    const float* B = (bx < 64) ? Bg : Bu;
    int nB = (bx & 63) * 128;
    gemm_core<0>(A, 2048, B, C, nullptr, 2048, INTER, nB, 2 * INTER, bx * 128);
}

// Reductions over 4 split-K partials, float4-vectorized.
// nElems = ROWS*N (multiple of 1024). RES: add Aux.
template <bool RES>
__global__ void __launch_bounds__(256) reduce4_kernel(
    const float* __restrict__ P, const float* __restrict__ Aux,
    float* __restrict__ C, int nElems)
{
    int i = (blockIdx.x * 256 + threadIdx.x) * 4;
    if (i >= nElems) return;
    float4 a = *reinterpret_cast<const float4*>(P + i);
    float4 b = *reinterpret_cast<const float4*>(P + nElems + i);
    float4 c = *reinterpret_cast<const float4*>(P + 2 * (size_t)nElems + i);
    float4 d = *reinterpret_cast<const float4*>(P + 3 * (size_t)nElems + i);
    float4 r;
    r.x = (a.x + b.x) + (c.x + d.x);
    r.y = (a.y + b.y) + (c.y + d.y);
    r.z = (a.z + b.z) + (c.z + d.z);
    r.w = (a.w + b.w) + (c.w + d.w);
    if (RES) {
        float4 x = *reinterpret_cast<const float4*>(Aux + i);
        r.x += x.x; r.y += x.y; r.z += x.z; r.w += x.w;
    }
    *reinterpret_cast<float4*>(C + i) = r;
}

// act[r][c] = silu(gu[r][c]) * gu[r][c+8192]
__global__ void __launch_bounds__(256) silu_mul_kernel(
    const float* __restrict__ gu, float* __restrict__ act)
{
    int i = blockIdx.x * 256 + threadIdx.x;
    int r = i >> 13, c = i & 8191;
    float g = gu[(size_t)r * (2 * INTER) + c];
    float u = gu[(size_t)r * (2 * INTER) + INTER + c];
    act[i] = (g / (1.f + expf(-g))) * u;
}

// ---------------------------------------------------------------------------
// Norm / copy / rope / gather / logsoftmax
// ---------------------------------------------------------------------------
__global__ void __launch_bounds__(256) rms_concat_kernel(
    const float* __restrict__ emb, const float* __restrict__ hs,
    const float* __restrict__ w_in, const float* __restrict__ w_hid,
    float* __restrict__ normed)
{
    const int row = blockIdx.x;
    const int tid = threadIdx.x;
    const float* x1 = emb + (size_t)row * HIDDEN;
    const float* x2 = hs + (size_t)row * HIDDEN;
    float s1 = 0.f, s2 = 0.f;
    for (int i = tid; i < HIDDEN; i += 256) {
        float a = x1[i]; s1 += a * a;
        float b = x2[i]; s2 += b * b;
    }
    float r1 = block_sum(s1);
    float r2 = block_sum(s2);
    float inv1 = rsqrtf(r1 / (float)HIDDEN + EPS);
    float inv2 = rsqrtf(r2 / (float)HIDDEN + EPS);
    float* o = normed + (size_t)row * (2 * HIDDEN);
    for (int i = tid; i < HIDDEN; i += 256) {
        o[i]          = x1[i] * inv1 * w_in[i];
        o[HIDDEN + i] = x2[i] * inv2 * w_hid[i];
    }
}

__global__ void __launch_bounds__(256) rms_kernel(
    const float* __restrict__ x, const float* __restrict__ w, float* __restrict__ y)
{
    const int row = blockIdx.x;
    const int tid = threadIdx.x;
    const float* xr = x + (size_t)row * HIDDEN;
    float s = 0.f;
    for (int i = tid; i < HIDDEN; i += 256) { float a = xr[i]; s += a * a; }
    float r = block_sum(s);
    float inv = rsqrtf(r / (float)HIDDEN + EPS);
    float* yr = y + (size_t)row * HIDDEN;
    for (int i = tid; i < HIDDEN; i += 256) yr[i] = xr[i] * inv * w[i];
}

__global__ void __launch_bounds__(256) gather_rms_kernel(
    const float* __restrict__ hs, const int* __restrict__ lt,
    const float* __restrict__ w, float* __restrict__ out_gathered,
    float* __restrict__ fn)
{
    const int row = blockIdx.x;
    const int tid = threadIdx.x;
    const int b = row >> 6;
    const int src_s = lt[row];
    const float* x = hs + ((size_t)b * SEQ + src_s) * HIDDEN;
    float s = 0.f;
    for (int i = tid; i < HIDDEN; i += 256) { float a = x[i]; s += a * a; }
    float r = block_sum(s);
    float inv = rsqrtf(r / (float)HIDDEN + EPS);
    float* og = out_gathered + (size_t)row * HIDDEN;
    float* fr = fn + (size_t)row * HIDDEN;
    for (int i = tid; i < HIDDEN; i += 256) {
        float a = x[i];
        og[i] = a;
        fr[i] = a * inv * w[i];
    }
}

__global__ void __launch_bounds__(256) copy_past_kernel(
    const float* __restrict__ past, float* __restrict__ present)
{
    const int idx = blockIdx.x * 256 + threadIdx.x;  // 2,097,152 float4
    const int lane = idx & 31;
    const int row = idx >> 5;
    const int t = row & 2047;
    const int bch = row >> 11;
    const float4* src = reinterpret_cast<const float4*>(past) + idx;
    float4* dst = reinterpret_cast<float4*>(present) + ((size_t)bch * TTOT + t) * 32 + lane;
    *dst = *src;
}

__global__ void __launch_bounds__(64) rope_store_kernel(
    float* __restrict__ qkv, const float* __restrict__ rope,
    const int* __restrict__ pos_ids, float* __restrict__ present)
{
    const int bs = blockIdx.x;
    const int h = blockIdx.y;
    const int d = threadIdx.x;
    const int b = bs >> 6, s = bs & 63;
    const int pos = pos_ids[bs];
    const float c = rope[(size_t)pos * 128 + d];
    const float sn = rope[(size_t)pos * 128 + 64 + d];
    float* row = qkv + (size_t)bs * 3072;
    if (h < 16) {
        float* base = row + h * 128;
        float x1 = base[d], x2 = base[d + 64];
        base[d] = x1 * c - x2 * sn;
        base[d + 64] = x2 * c + x1 * sn;
    } else if (h < 20) {
        const int kh = h - 16;
        const float* base = row + 2048 + kh * 128;
        float x1 = base[d], x2 = base[d + 64];
        float* dst = present + (((size_t)(b * 2 + 0) * NKV + kh) * TTOT + PAST + s) * HDIM;
        dst[d] = x1 * c - x2 * sn;
        dst[d + 64] = x2 * c + x1 * sn;
    } else {
        const int vh = h - 20;
        const float* base = row + 2560 + vh * 128;
        float* dst = present + (((size_t)(b * 2 + 1) * NKV + vh) * TTOT + PAST + s) * HDIM;
        dst[d] = base[d];
        dst[d + 64] = base[d + 64];
    }
}

// ---------------------------------------------------------------------------
// Attention (fp32; q from g_qkv stride 3072)
// ---------------------------------------------------------------------------
#define QS_STRIDE 132
#define SC_STRIDE 65
#define ATTN_SMEM ((32 * QS_STRIDE + 64 * QS_STRIDE + 64 * QS_STRIDE + 32 * SC_STRIDE + 64) * 4)

__global__ void __launch_bounds__(256) attn_kernel(
    const float* __restrict__ qkv, const float* __restrict__ kv,
    const int* __restrict__ ctx_len, float* __restrict__ out)
{
    extern __shared__ float sm[];
    float* qs = sm;
    float* ks = qs + 32 * QS_STRIDE;
    float* vs = ks + 64 * QS_STRIDE;
    float* sc = vs + 64 * QS_STRIDE;
    float* corr = sc + 32 * SC_STRIDE;
    float* lsm = corr + 32;

    const int tid = threadIdx.x;
    const int blk = blockIdx.x;
    const int qb = blk & 7;
    const int kvh = (blk >> 3) & 3;
    const int b = blk >> 5;

    for (int i = tid; i < 32 * 128; i += 256) {
        int ql = i >> 7, d = i & 127;
        int qid = qb * 32 + ql;
        int gi = qid >> 6, s = qid & 63;
        qs[ql * QS_STRIDE + d] =
            qkv[(size_t)(b * SEQ + s) * 3072 + (kvh * 4 + gi) * 128 + d];
    }

    float acc[16];
#pragma unroll
    for (int i = 0; i < 16; i++) acc[i] = 0.f;
    float m = -INFINITY, l = 0.f;

    const float* Kb = kv + (((size_t)(b * 2 + 0)) * NKV + kvh) * TTOT * HDIM;
    const float* Vb = kv + (((size_t)(b * 2 + 1)) * NKV + kvh) * TTOT * HDIM;
    const int ctx = ctx_len[b];

    const int ql_s = tid >> 3;
    const int ktg = tid & 7;
    const int qid_s = qb * 32 + ql_s;
    const int s_q = qid_s & 63;
    const int dg = (tid & 7) * 16;

    for (int t0 = 0; t0 < TTOT; t0 += 64) {
        __syncthreads();
        for (int i = tid * 4; i < 64 * 128; i += 1024) {
            int r = i >> 7, d = i & 127;
            *reinterpret_cast<float4*>(&ks[r * QS_STRIDE + d]) =
                *reinterpret_cast<const float4*>(&Kb[(size_t)(t0 + r) * HDIM + d]);
            *reinterpret_cast<float4*>(&vs[r * QS_STRIDE + d]) =
                *reinterpret_cast<const float4*>(&Vb[(size_t)(t0 + r) * HDIM + d]);
        }
        __syncthreads();
        {
            const float* qrow = &qs[ql_s * QS_STRIDE];
#pragma unroll
            for (int j = 0; j < 8; j++) {
                int kt = ktg + 8 * j;
                const float* krow = &ks[kt * QS_STRIDE];
                float dot = 0.f;
#pragma unroll
                for (int d = 0; d < 128; d += 4) {
                    float4 qv = *reinterpret_cast<const float4*>(&qrow[d]);
                    float4 kk = *reinterpret_cast<const float4*>(&krow[d]);
                    dot = fmaf(qv.x, kk.x, dot);
                    dot = fmaf(qv.y, kk.y, dot);
                    dot = fmaf(qv.z, kk.z, dot);
                    dot = fmaf(qv.w, kk.w, dot);
                }
                int t = t0 + kt;
                bool valid = (t < PAST) ? (t < ctx) : ((t - PAST) <= s_q);
                sc[ql_s * SC_STRIDE + kt] =
                    valid ? dot * 0.08838834764831845f : -INFINITY;
            }
        }
        __syncthreads();
        if (tid < 32) {
            float mt = -INFINITY;
#pragma unroll 8
            for (int j = 0; j < 64; j++) mt = fmaxf(mt, sc[tid * SC_STRIDE + j]);
            float mnew = fmaxf(m, mt);
            float c, sum = 0.f;
            if (mnew == -INFINITY) {
                c = 1.f;
                for (int j = 0; j < 64; j++) sc[tid * SC_STRIDE + j] = 0.f;
            } else {
                c = __expf(m - mnew);
#pragma unroll 8
                for (int j = 0; j < 64; j++) {
                    float p = __expf(sc[tid * SC_STRIDE + j] - mnew);
                    sc[tid * SC_STRIDE + j] = p;
                    sum += p;
                }
            }
            l = l * c + sum;
            m = mnew;
            corr[tid] = c;
        }
        __syncthreads();
        {
            float c = corr[ql_s];
#pragma unroll
            for (int i = 0; i < 16; i++) acc[i] *= c;
            for (int kt = 0; kt < 64; kt++) {
                float p = sc[ql_s * SC_STRIDE + kt];
                const float* vrow = &vs[kt * QS_STRIDE + dg];
#pragma unroll
                for (int i = 0; i < 16; i += 4) {
                    float4 vv = *reinterpret_cast<const float4*>(&vrow[i]);
                    acc[i + 0] = fmaf(p, vv.x, acc[i + 0]);
                    acc[i + 1] = fmaf(p, vv.y, acc[i + 1]);
                    acc[i + 2] = fmaf(p, vv.z, acc[i + 2]);
                    acc[i + 3] = fmaf(p, vv.w, acc[i + 3]);
                }
            }
        }
    }
    if (tid < 32) lsm[tid] = l;
    __syncthreads();
    {
        float linv = 1.f / lsm[ql_s];
        int gi = qid_s >> 6, s = qid_s & 63;
        float* orow = out + (((size_t)(b * SEQ + s)) * NQ + (kvh * 4 + gi)) * HDIM + dg;
#pragma unroll
        for (int i = 0; i < 16; i++) orow[i] = acc[i] * linv;
    }
}

__global__ void __launch_bounds__(256) logsoftmax_kernel(float* __restrict__ x)
{
    const int row = blockIdx.x;
    const int tid = threadIdx.x;
    float* xr = x + (size_t)row * VOCAB;
    float mv = -INFINITY;
    for (int i = tid; i < VOCAB; i += 256) mv = fmaxf(mv, xr[i]);
    float M = block_max(mv);
    float s = 0.f;
    for (int i = tid; i < VOCAB; i += 256) s += __expf(xr[i] - M);
    float S = block_sum(s);
    float lse = M + logf(S);
    for (int i = tid; i < VOCAB; i += 256) xr[i] = xr[i] - lse;
}

// ---------------------------------------------------------------------------
// Launch
// ---------------------------------------------------------------------------
extern "C" void kernel_launch(void* const* d_in, const int* in_sizes, int n_in,
                              void* d_out, int out_size)
{
    const float* inputs_embeds = (const float*)d_in[0];
    const float* past_kv       = (const float*)d_in[1];
    const float* rope          = (const float*)d_in[2];
    const int*   ctx_len       = (const int*)d_in[3];
    const int*   last_ids      = (const int*)d_in[5];
    const float* hsi           = (const float*)d_in[6];
    const float* hsd           = (const float*)d_in[7];
    const int*   pos_id        = (const int*)d_in[8];
    const float* W_fc   = (const float*)d_in[10];
    const float* W_q    = (const float*)d_in[11];
    const float* W_k    = (const float*)d_in[12];
    const float* W_v    = (const float*)d_in[13];
    const float* W_o    = (const float*)d_in[14];
    const float* W_gate = (const float*)d_in[15];
    const float* W_up   = (const float*)d_in[16];
    const float* W_down = (const float*)d_in[17];
    const float* W_lm   = (const float*)d_in[18];
    const float* w_hidden = (const float*)d_in[19];
    const float* w_input  = (const float*)d_in[20];
    const float* w_post   = (const float*)d_in[21];
    const float* w_final  = (const float*)d_in[22];

    float* out = (float*)d_out;
    float* out_logits   = out;
    float* out_gathered = out + LOGITS_ELEMS;
    float* out_present  = out + PRESENT_OFF;

    void* p;
    cudaGetSymbolAddress(&p, g_hs);     float* hs   = (float*)p;
    cudaGetSymbolAddress(&p, g_normed); float* nrm  = (float*)p;
    cudaGetSymbolAddress(&p, g_qkv);    float* qkv  = (float*)p;
    cudaGetSymbolAddress(&p, g_attn);   float* attnb= (float*)p;
    cudaGetSymbolAddress(&p, g_hn);     float* hn   = (float*)p;
    cudaGetSymbolAddress(&p, g_gu);     float* gu   = (float*)p;
    cudaGetSymbolAddress(&p, g_act);    float* actb = (float*)p;
    cudaGetSymbolAddress(&p, g_fn);     float* fnb  = (float*)p;
    cudaGetSymbolAddress(&p, g_part);   float* part = (float*)p;

    cudaFuncSetAttribute(attn_kernel, cudaFuncAttributeMaxDynamicSharedMemorySize, ATTN_SMEM);
    cudaFuncSetAttribute(tgemm<0>, cudaFuncAttributeMaxDynamicSharedMemorySize, GSMEM);
    cudaFuncSetAttribute(tgemm_split, cudaFuncAttributeMaxDynamicSharedMemorySize, GSMEM);
    cudaFuncSetAttribute(tgemm_qkv_split, cudaFuncAttributeMaxDynamicSharedMemorySize, GSMEM);
    cudaFuncSetAttribute(tgemm_gu, cudaFuncAttributeMaxDynamicSharedMemorySize, GSMEM);

    // 1. hs = draft + hsi @ W_fc   (split-K 4: 128 blocks)
    tgemm_split<<<dim3(16, 2, 4), 256, GSMEM>>>(hsi, 6144, W_fc, part, 1536, HIDDEN, HIDDEN);
    reduce4_kernel<true><<<512, 256>>>(part, hsd, hs, ROWS * HIDDEN);
    // 2. normed = [rms(emb), rms(hs)]
    rms_concat_kernel<<<ROWS, 256>>>(inputs_embeds, hs, w_input, w_hidden, nrm);
    // 3. fused qkv (split-K 4: 192 blocks)
    tgemm_qkv_split<<<dim3(24, 2, 4), 256, GSMEM>>>(nrm, W_q, W_k, W_v, part);
    reduce4_kernel<false><<<768, 256>>>(part, nullptr, qkv, ROWS * 3072);
    // 4. present
    copy_past_kernel<<<8192, 256>>>(past_kv, out_present);
    rope_store_kernel<<<dim3(256, 24), 64>>>(qkv, rope, pos_id, out_present);
    // 5. attention
    attn_kernel<<<128, 256, ATTN_SMEM>>>(qkv, out_present, ctx_len, attnb);
    // 6. hs += attn @ W_o  (split-K 4: 128 blocks)
    tgemm_split<<<dim3(16, 2, 4), 256, GSMEM>>>(attnb, 2048, W_o, part, 512, HIDDEN, HIDDEN);
    reduce4_kernel<true><<<512, 256>>>(part, hs, hs, ROWS * HIDDEN);
    // 7. MLP
    rms_kernel<<<ROWS, 256>>>(hs, w_post, hn);
    tgemm_gu<<<dim3(128, 2), 256, GSMEM>>>(hn, W_gate, W_up, gu);
    silu_mul_kernel<<<8192, 256>>>(gu, actb);
    tgemm_split<<<dim3(16, 2, 4), 256, GSMEM>>>(actb, INTER, W_down, part, 2048, HIDDEN, HIDDEN);
    reduce4_kernel<true><<<512, 256>>>(part, hs, hs, ROWS * HIDDEN);
    // 8. gather + final norm
    gather_rms_kernel<<<ROWS, 256>>>(hs, last_ids, w_final, out_gathered, fnb);
    // 9. LM head + log_softmax
    tgemm<0><<<dim3(250, 2), 256, GSMEM>>>(fnb, W_lm, out_logits, nullptr, 2048, VOCAB, VOCAB);
    logsoftmax_kernel<<<ROWS, 256>>>(out_logits);
}

// round 6
// speedup vs baseline: 4.9440x; 1.2062x over previous
#include <cuda_runtime.h>
#include <cuda_bf16.h>
#include <math.h>
#include <stdint.h>

#define BATCH 4
#define SEQ 64
#define PAST 2048
#define TTOT 2112
#define HIDDEN 2048
#define NQ 16
#define NKV 4
#define HDIM 128
#define INTER 8192
#define VOCAB 32000
#define ROWS 256
#define EPS 1e-6f

#define LOGITS_ELEMS (ROWS * VOCAB)
#define GATHERED_ELEMS (ROWS * HIDDEN)
#define PRESENT_OFF (LOGITS_ELEMS + GATHERED_ELEMS)

// ---------------------------------------------------------------------------
// Scratch (device globals)
// ---------------------------------------------------------------------------
__device__ float g_hs[ROWS * HIDDEN];
__device__ float g_normed[ROWS * 2 * HIDDEN];
__device__ float g_qkv[ROWS * 3072];
__device__ float g_attn[ROWS * NQ * HDIM];
__device__ float g_hn[ROWS * HIDDEN];
__device__ float g_gu[ROWS * 2 * INTER];
__device__ float g_act[ROWS * INTER];
__device__ float g_fn[ROWS * HIDDEN];
__device__ float g_part[4 * ROWS * 3072];       // split-K / attn partials
__device__ float g_ml[3 * ROWS * NQ * 2];       // attn (m,l) partials

// ---------------------------------------------------------------------------
// Helpers
// ---------------------------------------------------------------------------
__device__ __forceinline__ uint32_t smem_u32(const void* p) {
    uint32_t a;
    asm("{ .reg .u64 t; cvta.to.shared.u64 t, %1; cvt.u32.u64 %0, t; }"
        : "=r"(a) : "l"(p));
    return a;
}
__device__ __forceinline__ uint32_t tf32u(float x) {
    uint32_t r;
    asm("cvt.rna.tf32.f32 %0, %1;" : "=r"(r) : "f"(x));
    return r;
}
__device__ __forceinline__ void cpasync16(uint32_t s, const float* g) {
    asm volatile("cp.async.cg.shared.global [%0], [%1], 16;" :: "r"(s), "l"(g));
}
#define CP_COMMIT() asm volatile("cp.async.commit_group;" ::: "memory")
#define CP_WAIT_1() asm volatile("cp.async.wait_group 1;" ::: "memory")
#define CP_WAIT_0() asm volatile("cp.async.wait_group 0;" ::: "memory")

__device__ __forceinline__ void mma_tf32(float* c, const uint32_t* a, const uint32_t* b) {
    asm volatile(
        "mma.sync.aligned.m16n8k8.row.col.f32.tf32.tf32.f32 "
        "{%0,%1,%2,%3}, {%4,%5,%6,%7}, {%8,%9}, {%0,%1,%2,%3};"
        : "+f"(c[0]), "+f"(c[1]), "+f"(c[2]), "+f"(c[3])
        : "r"(a[0]), "r"(a[1]), "r"(a[2]), "r"(a[3]), "r"(b[0]), "r"(b[1]));
}

__device__ __forceinline__ float block_sum(float v) {
    __shared__ float sh[8];
    __shared__ float total;
    int tid = threadIdx.x;
#pragma unroll
    for (int o = 16; o > 0; o >>= 1) v += __shfl_xor_sync(0xffffffffu, v, o);
    if ((tid & 31) == 0) sh[tid >> 5] = v;
    __syncthreads();
    if (tid == 0) {
        float s = 0.f;
#pragma unroll
        for (int i = 0; i < 8; i++) s += sh[i];
        total = s;
    }
    __syncthreads();
    float r = total;
    __syncthreads();
    return r;
}
__device__ __forceinline__ float block_max(float v) {
    __shared__ float sh[8];
    __shared__ float total;
    int tid = threadIdx.x;
#pragma unroll
    for (int o = 16; o > 0; o >>= 1) v = fmaxf(v, __shfl_xor_sync(0xffffffffu, v, o));
    if ((tid & 31) == 0) sh[tid >> 5] = v;
    __syncthreads();
    if (tid == 0) {
        float s = -INFINITY;
#pragma unroll
        for (int i = 0; i < 8; i++) s = fmaxf(s, sh[i]);
        total = s;
    }
    __syncthreads();
    float r = total;
    __syncthreads();
    return r;
}

// ---------------------------------------------------------------------------
// tf32 GEMM core: 128x128 C tile, 256 threads, 3-stage cp.async pipeline.
// A row-major (lda), pre-offset to k start. B [kLen, ldB] cols nB..
// tf32 rounding (RNA) applied on consume. kLen multiple of 32 (>= 64).
// EPI 0: C = acc ; EPI 1: C = acc + Aux
// ---------------------------------------------------------------------------
#define A_ST 4608           // floats per A stage (128 x 36)
#define B_ST 4352           // floats per B stage (32 x 136)
#define STAGE_FL (A_ST + B_ST)
#define GSMEM (3 * STAGE_FL * 4)   // 107,520 B

__device__ __forceinline__ void gemm_issue(
    uint32_t smBase, int stage, const float* __restrict__ A, int lda, int mBase,
    const float* __restrict__ B, int ldB, int nB, int k0, int tid)
{
#pragma unroll
    for (int i = 0; i < 4; i++) {
        int fi = tid + 256 * i;
        int ar = fi >> 3, ac = (fi & 7) << 2;
        int br = fi >> 5, bc = (fi & 31) << 2;
        uint32_t sa = smBase + (uint32_t)(stage * STAGE_FL + ar * 36 + ac) * 4u;
        uint32_t sb = smBase + (uint32_t)(stage * STAGE_FL + A_ST + br * 136 + bc) * 4u;
        cpasync16(sa, A + (size_t)(mBase + ar) * lda + k0 + ac);
        cpasync16(sb, B + (size_t)(k0 + br) * ldB + nB + bc);
    }
    CP_COMMIT();
}

template <int EPI>
__device__ __forceinline__ void gemm_core(
    const float* __restrict__ A, int lda,
    const float* __restrict__ B,
    float* __restrict__ C, const float* __restrict__ Aux,
    int kLen, int ldB, int nB, int ldC, int nC)
{
    extern __shared__ float sm[];
    const uint32_t smBase = smem_u32(sm);

    const int tid = threadIdx.x;
    const int lane = tid & 31;
    const int wid = tid >> 5;
    const int warpM = wid & 1;
    const int warpN = wid >> 1;
    const int gid = lane >> 2;
    const int tig = lane & 3;
    const int mBase = blockIdx.y * 128;

    float acc[4][4][4];
#pragma unroll
    for (int a = 0; a < 4; a++)
#pragma unroll
        for (int b = 0; b < 4; b++)
#pragma unroll
            for (int c = 0; c < 4; c++) acc[a][b][c] = 0.f;

    const int nStg = kLen >> 5;
    gemm_issue(smBase, 0, A, lda, mBase, B, ldB, nB, 0, tid);
    gemm_issue(smBase, 1, A, lda, mBase, B, ldB, nB, 32, tid);

    int buf = 0;
    for (int i = 0; i < nStg; i++) {
        if (i + 1 < nStg) { CP_WAIT_1(); } else { CP_WAIT_0(); }
        __syncthreads();
        if (i + 2 < nStg) {
            int nb = i + 2;
            gemm_issue(smBase, nb - (nb / 3) * 3, A, lda, mBase, B, ldB, nB, nb * 32, tid);
        }
        const float* AsR = sm + buf * STAGE_FL;
        const float* BsR = AsR + A_ST;
#pragma unroll
        for (int ks = 0; ks < 32; ks += 8) {
            uint32_t af[4][4];
#pragma unroll
            for (int mi = 0; mi < 4; mi++) {
                int r0 = (warpM * 64 + mi * 16 + gid) * 36;
                af[mi][0] = tf32u(AsR[r0 + ks + tig]);
                af[mi][1] = tf32u(AsR[r0 + 288 + ks + tig]);
                af[mi][2] = tf32u(AsR[r0 + ks + 4 + tig]);
                af[mi][3] = tf32u(AsR[r0 + 288 + ks + 4 + tig]);
            }
            uint32_t bf[4][2];
#pragma unroll
            for (int nj = 0; nj < 4; nj++) {
                int c0 = warpN * 32 + nj * 8 + gid;
                bf[nj][0] = tf32u(BsR[(ks + tig) * 136 + c0]);
                bf[nj][1] = tf32u(BsR[(ks + 4 + tig) * 136 + c0]);
            }
#pragma unroll
            for (int mi = 0; mi < 4; mi++)
#pragma unroll
                for (int nj = 0; nj < 4; nj++)
                    mma_tf32(acc[mi][nj], af[mi], bf[nj]);
        }
        buf = (buf == 2) ? 0 : buf + 1;
    }

#pragma unroll
    for (int mi = 0; mi < 4; mi++) {
        int row = mBase + warpM * 64 + mi * 16 + gid;
#pragma unroll
        for (int nj = 0; nj < 4; nj++) {
            int col = nC + warpN * 32 + nj * 8 + tig * 2;
            float2 v0 = make_float2(acc[mi][nj][0], acc[mi][nj][1]);
            float2 v1 = make_float2(acc[mi][nj][2], acc[mi][nj][3]);
            size_t o0 = (size_t)row * ldC + col;
            size_t o1 = (size_t)(row + 8) * ldC + col;
            if (EPI == 1) {
                float2 x0 = *reinterpret_cast<const float2*>(Aux + o0);
                float2 x1 = *reinterpret_cast<const float2*>(Aux + o1);
                v0.x += x0.x; v0.y += x0.y;
                v1.x += x1.x; v1.y += x1.y;
            }
            *reinterpret_cast<float2*>(C + o0) = v0;
            *reinterpret_cast<float2*>(C + o1) = v1;
        }
    }
}

// Unsplit GEMM (gu select / lm)
template <int EPI>
__global__ void __launch_bounds__(256, 2) tgemm(
    const float* __restrict__ A, const float* __restrict__ B,
    float* __restrict__ C, const float* __restrict__ Aux, int K, int ldB, int ldC)
{
    gemm_core<EPI>(A, K, B, C, Aux, K, ldB, blockIdx.x * 128, ldC, blockIdx.x * 128);
}

// Split-K GEMM: grid (N/128, 2, 4). Partial z -> P + z*ROWS*ldC.
__global__ void __launch_bounds__(256, 2) tgemm_split(
    const float* __restrict__ A, int lda, const float* __restrict__ B,
    float* __restrict__ P, int kLen, int ldB, int ldC)
{
    int z = blockIdx.z;
    gemm_core<0>(A + (size_t)z * kLen, lda,
                 B + (size_t)z * kLen * ldB,
                 P + (size_t)z * ROWS * ldC, nullptr,
                 kLen, ldB, blockIdx.x * 128, ldC, blockIdx.x * 128);
}

// Split-K fused q/k/v: grid (24, 2, 4).
__global__ void __launch_bounds__(256, 2) tgemm_qkv_split(
    const float* __restrict__ A, const float* __restrict__ Bq,
    const float* __restrict__ Bk, const float* __restrict__ Bv, float* __restrict__ P)
{
    int bx = blockIdx.x, z = blockIdx.z;
    const float* B; int ldB, nB;
    if (bx < 16)      { B = Bq; ldB = 2048; nB = bx * 128; }
    else if (bx < 20) { B = Bk; ldB = 512;  nB = (bx - 16) * 128; }
    else              { B = Bv; ldB = 512;  nB = (bx - 20) * 128; }
    gemm_core<0>(A + (size_t)z * 1024, 4096,
                 B + (size_t)z * 1024 * ldB,
                 P + (size_t)z * ROWS * 3072, nullptr,
                 1024, ldB, nB, 3072, bx * 128);
}

// Fused gate|up: grid (128, 2)
__global__ void __launch_bounds__(256, 2) tgemm_gu(
    const float* __restrict__ A, const float* __restrict__ Bg,
    const float* __restrict__ Bu, float* __restrict__ C)
{
    int bx = blockIdx.x;
    const float* B = (bx < 64) ? Bg : Bu;
    int nB = (bx & 63) * 128;
    gemm_core<0>(A, 2048, B, C, nullptr, 2048, INTER, nB, 2 * INTER, bx * 128);
}

// Reduce 4 split-K partials (+ optional residual), float4-vectorized.
template <bool RES>
__global__ void __launch_bounds__(256) reduce4_kernel(
    const float* __restrict__ P, const float* __restrict__ Aux,
    float* __restrict__ C, int nElems)
{
    int i = (blockIdx.x * 256 + threadIdx.x) * 4;
    if (i >= nElems) return;
    float4 a = *reinterpret_cast<const float4*>(P + i);
    float4 b = *reinterpret_cast<const float4*>(P + nElems + i);
    float4 c = *reinterpret_cast<const float4*>(P + 2 * (size_t)nElems + i);
    float4 d = *reinterpret_cast<const float4*>(P + 3 * (size_t)nElems + i);
    float4 r;
    r.x = (a.x + b.x) + (c.x + d.x);
    r.y = (a.y + b.y) + (c.y + d.y);
    r.z = (a.z + b.z) + (c.z + d.z);
    r.w = (a.w + b.w) + (c.w + d.w);
    if (RES) {
        float4 x = *reinterpret_cast<const float4*>(Aux + i);
        r.x += x.x; r.y += x.y; r.z += x.z; r.w += x.w;
    }
    *reinterpret_cast<float4*>(C + i) = r;
}

__global__ void __launch_bounds__(256) silu_mul_kernel(
    const float* __restrict__ gu, float* __restrict__ act)
{
    int i = blockIdx.x * 256 + threadIdx.x;
    int r = i >> 13, c = i & 8191;
    float g = gu[(size_t)r * (2 * INTER) + c];
    float u = gu[(size_t)r * (2 * INTER) + INTER + c];
    act[i] = (g / (1.f + expf(-g))) * u;
}

// ---------------------------------------------------------------------------
// Norm / copy / rope / gather / logsoftmax
// ---------------------------------------------------------------------------
__global__ void __launch_bounds__(256) rms_concat_kernel(
    const float* __restrict__ emb, const float* __restrict__ hs,
    const float* __restrict__ w_in, const float* __restrict__ w_hid,
    float* __restrict__ normed)
{
    const int row = blockIdx.x;
    const int tid = threadIdx.x;
    const float* x1 = emb + (size_t)row * HIDDEN;
    const float* x2 = hs + (size_t)row * HIDDEN;
    float s1 = 0.f, s2 = 0.f;
    for (int i = tid; i < HIDDEN; i += 256) {
        float a = x1[i]; s1 += a * a;
        float b = x2[i]; s2 += b * b;
    }
    float r1 = block_sum(s1);
    float r2 = block_sum(s2);
    float inv1 = rsqrtf(r1 / (float)HIDDEN + EPS);
    float inv2 = rsqrtf(r2 / (float)HIDDEN + EPS);
    float* o = normed + (size_t)row * (2 * HIDDEN);
    for (int i = tid; i < HIDDEN; i += 256) {
        o[i]          = x1[i] * inv1 * w_in[i];
        o[HIDDEN + i] = x2[i] * inv2 * w_hid[i];
    }
}

__global__ void __launch_bounds__(256) rms_kernel(
    const float* __restrict__ x, const float* __restrict__ w, float* __restrict__ y)
{
    const int row = blockIdx.x;
    const int tid = threadIdx.x;
    const float* xr = x + (size_t)row * HIDDEN;
    float s = 0.f;
    for (int i = tid; i < HIDDEN; i += 256) { float a = xr[i]; s += a * a; }
    float r = block_sum(s);
    float inv = rsqrtf(r / (float)HIDDEN + EPS);
    float* yr = y + (size_t)row * HIDDEN;
    for (int i = tid; i < HIDDEN; i += 256) yr[i] = xr[i] * inv * w[i];
}

__global__ void __launch_bounds__(256) gather_rms_kernel(
    const float* __restrict__ hs, const int* __restrict__ lt,
    const float* __restrict__ w, float* __restrict__ out_gathered,
    float* __restrict__ fn)
{
    const int row = blockIdx.x;
    const int tid = threadIdx.x;
    const int b = row >> 6;
    const int src_s = lt[row];
    const float* x = hs + ((size_t)b * SEQ + src_s) * HIDDEN;
    float s = 0.f;
    for (int i = tid; i < HIDDEN; i += 256) { float a = x[i]; s += a * a; }
    float r = block_sum(s);
    float inv = rsqrtf(r / (float)HIDDEN + EPS);
    float* og = out_gathered + (size_t)row * HIDDEN;
    float* fr = fn + (size_t)row * HIDDEN;
    for (int i = tid; i < HIDDEN; i += 256) {
        float a = x[i];
        og[i] = a;
        fr[i] = a * inv * w[i];
    }
}

__global__ void __launch_bounds__(256) copy_past_kernel(
    const float* __restrict__ past, float* __restrict__ present)
{
    const int idx = blockIdx.x * 256 + threadIdx.x;  // 2,097,152 float4
    const int lane = idx & 31;
    const int row = idx >> 5;
    const int t = row & 2047;
    const int bch = row >> 11;
    const float4* src = reinterpret_cast<const float4*>(past) + idx;
    float4* dst = reinterpret_cast<float4*>(present) + ((size_t)bch * TTOT + t) * 32 + lane;
    *dst = *src;
}

__global__ void __launch_bounds__(64) rope_store_kernel(
    float* __restrict__ qkv, const float* __restrict__ rope,
    const int* __restrict__ pos_ids, float* __restrict__ present)
{
    const int bs = blockIdx.x;
    const int h = blockIdx.y;
    const int d = threadIdx.x;
    const int b = bs >> 6, s = bs & 63;
    const int pos = pos_ids[bs];
    const float c = rope[(size_t)pos * 128 + d];
    const float sn = rope[(size_t)pos * 128 + 64 + d];
    float* row = qkv + (size_t)bs * 3072;
    if (h < 16) {
        float* base = row + h * 128;
        float x1 = base[d], x2 = base[d + 64];
        base[d] = x1 * c - x2 * sn;
        base[d + 64] = x2 * c + x1 * sn;
    } else if (h < 20) {
        const int kh = h - 16;
        const float* base = row + 2048 + kh * 128;
        float x1 = base[d], x2 = base[d + 64];
        float* dst = present + (((size_t)(b * 2 + 0) * NKV + kh) * TTOT + PAST + s) * HDIM;
        dst[d] = x1 * c - x2 * sn;
        dst[d + 64] = x2 * c + x1 * sn;
    } else {
        const int vh = h - 20;
        const float* base = row + 2560 + vh * 128;
        float* dst = present + (((size_t)(b * 2 + 1) * NKV + vh) * TTOT + PAST + s) * HDIM;
        dst[d] = base[d];
        dst[d + 64] = base[d + 64];
    }
}

// ---------------------------------------------------------------------------
// Attention, flash-decode split: grid (128, 3). Chunk cz covers 11 key-tiles
// (704 positions). Writes unnormalized acc + (m,l) partials.
// ---------------------------------------------------------------------------
#define QS_STRIDE 132
#define SC_STRIDE 65
#define ATTN_SMEM ((32 * QS_STRIDE + 64 * QS_STRIDE + 64 * QS_STRIDE + 32 * SC_STRIDE + 64) * 4)
#define ACC_CHUNK (ROWS * NQ * HDIM)   // 524288
#define ML_CHUNK (ROWS * NQ * 2)       // 8192

__global__ void __launch_bounds__(256) attn_part_kernel(
    const float* __restrict__ qkv, const float* __restrict__ kv,
    const int* __restrict__ ctx_len, float* __restrict__ pacc, float* __restrict__ pml)
{
    extern __shared__ float sm[];
    float* qs = sm;
    float* ks = qs + 32 * QS_STRIDE;
    float* vs = ks + 64 * QS_STRIDE;
    float* sc = vs + 64 * QS_STRIDE;
    float* corr = sc + 32 * SC_STRIDE;

    const int tid = threadIdx.x;
    const int blk = blockIdx.x;
    const int cz = blockIdx.y;
    const int qb = blk & 7;
    const int kvh = (blk >> 3) & 3;
    const int b = blk >> 5;

    for (int i = tid; i < 32 * 128; i += 256) {
        int ql = i >> 7, d = i & 127;
        int qid = qb * 32 + ql;
        int gi = qid >> 6, s = qid & 63;
        qs[ql * QS_STRIDE + d] =
            qkv[(size_t)(b * SEQ + s) * 3072 + (kvh * 4 + gi) * 128 + d];
    }

    float acc[16];
#pragma unroll
    for (int i = 0; i < 16; i++) acc[i] = 0.f;
    float m = -INFINITY, l = 0.f;

    const float* Kb = kv + (((size_t)(b * 2 + 0)) * NKV + kvh) * TTOT * HDIM;
    const float* Vb = kv + (((size_t)(b * 2 + 1)) * NKV + kvh) * TTOT * HDIM;
    const int ctx = ctx_len[b];

    const int ql_s = tid >> 3;
    const int ktg = tid & 7;
    const int qid_s = qb * 32 + ql_s;
    const int s_q = qid_s & 63;
    const int dg = (tid & 7) * 16;

    const int tile0 = cz * 11;
    for (int ti = tile0; ti < tile0 + 11; ti++) {
        const int t0 = ti * 64;
        __syncthreads();
        for (int i = tid * 4; i < 64 * 128; i += 1024) {
            int r = i >> 7, d = i & 127;
            *reinterpret_cast<float4*>(&ks[r * QS_STRIDE + d]) =
                *reinterpret_cast<const float4*>(&Kb[(size_t)(t0 + r) * HDIM + d]);
            *reinterpret_cast<float4*>(&vs[r * QS_STRIDE + d]) =
                *reinterpret_cast<const float4*>(&Vb[(size_t)(t0 + r) * HDIM + d]);
        }
        __syncthreads();
        {
            const float* qrow = &qs[ql_s * QS_STRIDE];
#pragma unroll
            for (int j = 0; j < 8; j++) {
                int kt = ktg + 8 * j;
                const float* krow = &ks[kt * QS_STRIDE];
                float dot = 0.f;
#pragma unroll
                for (int d = 0; d < 128; d += 4) {
                    float4 qv = *reinterpret_cast<const float4*>(&qrow[d]);
                    float4 kk = *reinterpret_cast<const float4*>(&krow[d]);
                    dot = fmaf(qv.x, kk.x, dot);
                    dot = fmaf(qv.y, kk.y, dot);
                    dot = fmaf(qv.z, kk.z, dot);
                    dot = fmaf(qv.w, kk.w, dot);
                }
                int t = t0 + kt;
                bool valid = (t < PAST) ? (t < ctx) : ((t - PAST) <= s_q);
                sc[ql_s * SC_STRIDE + kt] =
                    valid ? dot * 0.08838834764831845f : -INFINITY;
            }
        }
        __syncthreads();
        if (tid < 32) {
            float mt = -INFINITY;
#pragma unroll 8
            for (int j = 0; j < 64; j++) mt = fmaxf(mt, sc[tid * SC_STRIDE + j]);
            float mnew = fmaxf(m, mt);
            float c, sum = 0.f;
            if (mnew == -INFINITY) {
                c = 1.f;
                for (int j = 0; j < 64; j++) sc[tid * SC_STRIDE + j] = 0.f;
            } else {
                c = __expf(m - mnew);
#pragma unroll 8
                for (int j = 0; j < 64; j++) {
                    float p = __expf(sc[tid * SC_STRIDE + j] - mnew);
                    sc[tid * SC_STRIDE + j] = p;
                    sum += p;
                }
            }
            l = l * c + sum;
            m = mnew;
            corr[tid] = c;
        }
        __syncthreads();
        {
            float c = corr[ql_s];
#pragma unroll
            for (int i = 0; i < 16; i++) acc[i] *= c;
            for (int kt = 0; kt < 64; kt++) {
                float p = sc[ql_s * SC_STRIDE + kt];
                const float* vrow = &vs[kt * QS_STRIDE + dg];
#pragma unroll
                for (int i = 0; i < 16; i += 4) {
                    float4 vv = *reinterpret_cast<const float4*>(&vrow[i]);
                    acc[i + 0] = fmaf(p, vv.x, acc[i + 0]);
                    acc[i + 1] = fmaf(p, vv.y, acc[i + 1]);
                    acc[i + 2] = fmaf(p, vv.z, acc[i + 2]);
                    acc[i + 3] = fmaf(p, vv.w, acc[i + 3]);
                }
            }
        }
    }
    // write partials
    if (tid < 32) {
        int qid = qb * 32 + tid;
        int gi = qid >> 6, s = qid & 63;
        int row = (b * SEQ + s) * NQ + (kvh * 4 + gi);
        pml[(size_t)cz * ML_CHUNK + row * 2 + 0] = m;
        pml[(size_t)cz * ML_CHUNK + row * 2 + 1] = l;
    }
    {
        int gi = qid_s >> 6, s = qid_s & 63;
        int row = (b * SEQ + s) * NQ + (kvh * 4 + gi);
        float* orow = pacc + (size_t)cz * ACC_CHUNK + (size_t)row * HDIM + dg;
#pragma unroll
        for (int i = 0; i < 16; i++) orow[i] = acc[i];
    }
}

// Merge 3 chunks. grid 4096, block 128.
__global__ void __launch_bounds__(128) attn_merge_kernel(
    const float* __restrict__ pacc, const float* __restrict__ pml,
    float* __restrict__ out)
{
    const int row = blockIdx.x;
    const int d = threadIdx.x;
    float m0 = pml[row * 2], l0 = pml[row * 2 + 1];
    float m1 = pml[ML_CHUNK + row * 2], l1 = pml[ML_CHUNK + row * 2 + 1];
    float m2 = pml[2 * ML_CHUNK + row * 2], l2 = pml[2 * ML_CHUNK + row * 2 + 1];
    float mg = fmaxf(m0, fmaxf(m1, m2));
    float w0 = __expf(m0 - mg), w1 = __expf(m1 - mg), w2 = __expf(m2 - mg);
    float L = l0 * w0 + l1 * w1 + l2 * w2;
    size_t o = (size_t)row * HDIM + d;
    float a = pacc[o] * w0 + pacc[ACC_CHUNK + o] * w1 + pacc[2 * (size_t)ACC_CHUNK + o] * w2;
    out[o] = a / L;
}

__global__ void __launch_bounds__(256) logsoftmax_kernel(float* __restrict__ x)
{
    const int row = blockIdx.x;
    const int tid = threadIdx.x;
    float* xr = x + (size_t)row * VOCAB;
    float mv = -INFINITY;
    for (int i = tid; i < VOCAB; i += 256) mv = fmaxf(mv, xr[i]);
    float M = block_max(mv);
    float s = 0.f;
    for (int i = tid; i < VOCAB; i += 256) s += __expf(xr[i] - M);
    float S = block_sum(s);
    float lse = M + logf(S);
    for (int i = tid; i < VOCAB; i += 256) xr[i] = xr[i] - lse;
}

// ---------------------------------------------------------------------------
// Launch
// ---------------------------------------------------------------------------
extern "C" void kernel_launch(void* const* d_in, const int* in_sizes, int n_in,
                              void* d_out, int out_size)
{
    const float* inputs_embeds = (const float*)d_in[0];
    const float* past_kv       = (const float*)d_in[1];
    const float* rope          = (const float*)d_in[2];
    const int*   ctx_len       = (const int*)d_in[3];
    const int*   last_ids      = (const int*)d_in[5];
    const float* hsi           = (const float*)d_in[6];
    const float* hsd           = (const float*)d_in[7];
    const int*   pos_id        = (const int*)d_in[8];
    const float* W_fc   = (const float*)d_in[10];
    const float* W_q    = (const float*)d_in[11];
    const float* W_k    = (const float*)d_in[12];
    const float* W_v    = (const float*)d_in[13];
    const float* W_o    = (const float*)d_in[14];
    const float* W_gate = (const float*)d_in[15];
    const float* W_up   = (const float*)d_in[16];
    const float* W_down = (const float*)d_in[17];
    const float* W_lm   = (const float*)d_in[18];
    const float* w_hidden = (const float*)d_in[19];
    const float* w_input  = (const float*)d_in[20];
    const float* w_post   = (const float*)d_in[21];
    const float* w_final  = (const float*)d_in[22];

    float* out = (float*)d_out;
    float* out_logits   = out;
    float* out_gathered = out + LOGITS_ELEMS;
    float* out_present  = out + PRESENT_OFF;

    void* p;
    cudaGetSymbolAddress(&p, g_hs);     float* hs   = (float*)p;
    cudaGetSymbolAddress(&p, g_normed); float* nrm  = (float*)p;
    cudaGetSymbolAddress(&p, g_qkv);    float* qkv  = (float*)p;
    cudaGetSymbolAddress(&p, g_attn);   float* attnb= (float*)p;
    cudaGetSymbolAddress(&p, g_hn);     float* hn   = (float*)p;
    cudaGetSymbolAddress(&p, g_gu);     float* gu   = (float*)p;
    cudaGetSymbolAddress(&p, g_act);    float* actb = (float*)p;
    cudaGetSymbolAddress(&p, g_fn);     float* fnb  = (float*)p;
    cudaGetSymbolAddress(&p, g_part);   float* part = (float*)p;
    cudaGetSymbolAddress(&p, g_ml);     float* ml   = (float*)p;

    cudaFuncSetAttribute(attn_part_kernel, cudaFuncAttributeMaxDynamicSharedMemorySize, ATTN_SMEM);
    cudaFuncSetAttribute(tgemm<0>, cudaFuncAttributeMaxDynamicSharedMemorySize, GSMEM);
    cudaFuncSetAttribute(tgemm_split, cudaFuncAttributeMaxDynamicSharedMemorySize, GSMEM);
    cudaFuncSetAttribute(tgemm_qkv_split, cudaFuncAttributeMaxDynamicSharedMemorySize, GSMEM);
    cudaFuncSetAttribute(tgemm_gu, cudaFuncAttributeMaxDynamicSharedMemorySize, GSMEM);

    // 1. hs = draft + hsi @ W_fc   (split-K 4)
    tgemm_split<<<dim3(16, 2, 4), 256, GSMEM>>>(hsi, 6144, W_fc, part, 1536, HIDDEN, HIDDEN);
    reduce4_kernel<true><<<512, 256>>>(part, hsd, hs, ROWS * HIDDEN);
    // 2. normed
    rms_concat_kernel<<<ROWS, 256>>>(inputs_embeds, hs, w_input, w_hidden, nrm);
    // 3. fused qkv (split-K 4)
    tgemm_qkv_split<<<dim3(24, 2, 4), 256, GSMEM>>>(nrm, W_q, W_k, W_v, part);
    reduce4_kernel<false><<<768, 256>>>(part, nullptr, qkv, ROWS * 3072);
    // 4. present
    copy_past_kernel<<<8192, 256>>>(past_kv, out_present);
    rope_store_kernel<<<dim3(256, 24), 64>>>(qkv, rope, pos_id, out_present);
    // 5. attention (flash-decode over 3 T-chunks)
    attn_part_kernel<<<dim3(128, 3), 256, ATTN_SMEM>>>(qkv, out_present, ctx_len, part, ml);
    attn_merge_kernel<<<4096, 128>>>(part, ml, attnb);
    // 6. hs += attn @ W_o  (split-K 4)
    tgemm_split<<<dim3(16, 2, 4), 256, GSMEM>>>(attnb, 2048, W_o, part, 512, HIDDEN, HIDDEN);
    reduce4_kernel<true><<<512, 256>>>(part, hs, hs, ROWS * HIDDEN);
    // 7. MLP
    rms_kernel<<<ROWS, 256>>>(hs, w_post, hn);
    tgemm_gu<<<dim3(128, 2), 256, GSMEM>>>(hn, W_gate, W_up, gu);
    silu_mul_kernel<<<8192, 256>>>(gu, actb);
    tgemm_split<<<dim3(16, 2, 4), 256, GSMEM>>>(actb, INTER, W_down, part, 2048, HIDDEN, HIDDEN);
    reduce4_kernel<true><<<512, 256>>>(part, hs, hs, ROWS * HIDDEN);
    // 8. gather + final norm
    gather_rms_kernel<<<ROWS, 256>>>(hs, last_ids, w_final, out_gathered, fnb);
    // 9. LM head + log_softmax
    tgemm<0><<<dim3(250, 2), 256, GSMEM>>>(fnb, W_lm, out_logits, nullptr, 2048, VOCAB, VOCAB);
    logsoftmax_kernel<<<ROWS, 256>>>(out_logits);
}

// round 7
// speedup vs baseline: 5.2301x; 1.0579x over previous
#include <cuda_runtime.h>
#include <cuda_bf16.h>
#include <math.h>
#include <stdint.h>

#define BATCH 4
#define SEQ 64
#define PAST 2048
#define TTOT 2112
#define HIDDEN 2048
#define NQ 16
#define NKV 4
#define HDIM 128
#define INTER 8192
#define VOCAB 32000
#define ROWS 256
#define EPS 1e-6f

#define LOGITS_ELEMS (ROWS * VOCAB)
#define GATHERED_ELEMS (ROWS * HIDDEN)
#define PRESENT_OFF (LOGITS_ELEMS + GATHERED_ELEMS)

// ---------------------------------------------------------------------------
// Scratch (device globals)
// ---------------------------------------------------------------------------
__device__ float g_hs[ROWS * HIDDEN];
__device__ float g_normed[ROWS * 2 * HIDDEN];
__device__ float g_qkv[ROWS * 3072];
__device__ float g_attn[ROWS * NQ * HDIM];
__device__ float g_hn[ROWS * HIDDEN];
__device__ float g_gu[ROWS * 2 * INTER];
__device__ float g_act[ROWS * INTER];
__device__ float g_fn[ROWS * HIDDEN];
__device__ float g_part[8 * ROWS * 3072];       // split-K (8) / attn acc partials
__device__ float g_ml[6 * ROWS * NQ * 2];       // attn (m,l) partials (6 chunks)

// ---------------------------------------------------------------------------
// Helpers
// ---------------------------------------------------------------------------
__device__ __forceinline__ uint32_t smem_u32(const void* p) {
    uint32_t a;
    asm("{ .reg .u64 t; cvta.to.shared.u64 t, %1; cvt.u32.u64 %0, t; }"
        : "=r"(a) : "l"(p));
    return a;
}
__device__ __forceinline__ uint32_t tf32u(float x) {
    uint32_t r;
    asm("cvt.rna.tf32.f32 %0, %1;" : "=r"(r) : "f"(x));
    return r;
}
__device__ __forceinline__ void cpasync16(uint32_t s, const float* g) {
    asm volatile("cp.async.cg.shared.global [%0], [%1], 16;" :: "r"(s), "l"(g));
}
#define CP_COMMIT() asm volatile("cp.async.commit_group;" ::: "memory")
#define CP_WAIT_1() asm volatile("cp.async.wait_group 1;" ::: "memory")
#define CP_WAIT_0() asm volatile("cp.async.wait_group 0;" ::: "memory")

__device__ __forceinline__ void mma_tf32(float* c, const uint32_t* a, const uint32_t* b) {
    asm volatile(
        "mma.sync.aligned.m16n8k8.row.col.f32.tf32.tf32.f32 "
        "{%0,%1,%2,%3}, {%4,%5,%6,%7}, {%8,%9}, {%0,%1,%2,%3};"
        : "+f"(c[0]), "+f"(c[1]), "+f"(c[2]), "+f"(c[3])
        : "r"(a[0]), "r"(a[1]), "r"(a[2]), "r"(a[3]), "r"(b[0]), "r"(b[1]));
}

__device__ __forceinline__ float block_sum(float v) {
    __shared__ float sh[8];
    __shared__ float total;
    int tid = threadIdx.x;
#pragma unroll
    for (int o = 16; o > 0; o >>= 1) v += __shfl_xor_sync(0xffffffffu, v, o);
    if ((tid & 31) == 0) sh[tid >> 5] = v;
    __syncthreads();
    if (tid == 0) {
        float s = 0.f;
#pragma unroll
        for (int i = 0; i < 8; i++) s += sh[i];
        total = s;
    }
    __syncthreads();
    float r = total;
    __syncthreads();
    return r;
}
__device__ __forceinline__ float block_max(float v) {
    __shared__ float sh[8];
    __shared__ float total;
    int tid = threadIdx.x;
#pragma unroll
    for (int o = 16; o > 0; o >>= 1) v = fmaxf(v, __shfl_xor_sync(0xffffffffu, v, o));
    if ((tid & 31) == 0) sh[tid >> 5] = v;
    __syncthreads();
    if (tid == 0) {
        float s = -INFINITY;
#pragma unroll
        for (int i = 0; i < 8; i++) s = fmaxf(s, sh[i]);
        total = s;
    }
    __syncthreads();
    float r = total;
    __syncthreads();
    return r;
}

// ---------------------------------------------------------------------------
// tf32 GEMM core: 128x128 C tile, 256 threads, 3-stage cp.async pipeline.
// ---------------------------------------------------------------------------
#define A_ST 4608
#define B_ST 4352
#define STAGE_FL (A_ST + B_ST)
#define GSMEM (3 * STAGE_FL * 4)

__device__ __forceinline__ void gemm_issue(
    uint32_t smBase, int stage, const float* __restrict__ A, int lda, int mBase,
    const float* __restrict__ B, int ldB, int nB, int k0, int tid)
{
#pragma unroll
    for (int i = 0; i < 4; i++) {
        int fi = tid + 256 * i;
        int ar = fi >> 3, ac = (fi & 7) << 2;
        int br = fi >> 5, bc = (fi & 31) << 2;
        uint32_t sa = smBase + (uint32_t)(stage * STAGE_FL + ar * 36 + ac) * 4u;
        uint32_t sb = smBase + (uint32_t)(stage * STAGE_FL + A_ST + br * 136 + bc) * 4u;
        cpasync16(sa, A + (size_t)(mBase + ar) * lda + k0 + ac);
        cpasync16(sb, B + (size_t)(k0 + br) * ldB + nB + bc);
    }
    CP_COMMIT();
}

template <int EPI>
__device__ __forceinline__ void gemm_core(
    const float* __restrict__ A, int lda,
    const float* __restrict__ B,
    float* __restrict__ C, const float* __restrict__ Aux,
    int kLen, int ldB, int nB, int ldC, int nC)
{
    extern __shared__ float sm[];
    const uint32_t smBase = smem_u32(sm);

    const int tid = threadIdx.x;
    const int lane = tid & 31;
    const int wid = tid >> 5;
    const int warpM = wid & 1;
    const int warpN = wid >> 1;
    const int gid = lane >> 2;
    const int tig = lane & 3;
    const int mBase = blockIdx.y * 128;

    float acc[4][4][4];
#pragma unroll
    for (int a = 0; a < 4; a++)
#pragma unroll
        for (int b = 0; b < 4; b++)
#pragma unroll
            for (int c = 0; c < 4; c++) acc[a][b][c] = 0.f;

    const int nStg = kLen >> 5;
    gemm_issue(smBase, 0, A, lda, mBase, B, ldB, nB, 0, tid);
    gemm_issue(smBase, 1, A, lda, mBase, B, ldB, nB, 32, tid);

    int buf = 0;
    for (int i = 0; i < nStg; i++) {
        if (i + 1 < nStg) { CP_WAIT_1(); } else { CP_WAIT_0(); }
        __syncthreads();
        if (i + 2 < nStg) {
            int nb = i + 2;
            gemm_issue(smBase, nb - (nb / 3) * 3, A, lda, mBase, B, ldB, nB, nb * 32, tid);
        }
        const float* AsR = sm + buf * STAGE_FL;
        const float* BsR = AsR + A_ST;
#pragma unroll
        for (int ks = 0; ks < 32; ks += 8) {
            uint32_t af[4][4];
#pragma unroll
            for (int mi = 0; mi < 4; mi++) {
                int r0 = (warpM * 64 + mi * 16 + gid) * 36;
                af[mi][0] = tf32u(AsR[r0 + ks + tig]);
                af[mi][1] = tf32u(AsR[r0 + 288 + ks + tig]);
                af[mi][2] = tf32u(AsR[r0 + ks + 4 + tig]);
                af[mi][3] = tf32u(AsR[r0 + 288 + ks + 4 + tig]);
            }
            uint32_t bf[4][2];
#pragma unroll
            for (int nj = 0; nj < 4; nj++) {
                int c0 = warpN * 32 + nj * 8 + gid;
                bf[nj][0] = tf32u(BsR[(ks + tig) * 136 + c0]);
                bf[nj][1] = tf32u(BsR[(ks + 4 + tig) * 136 + c0]);
            }
#pragma unroll
            for (int mi = 0; mi < 4; mi++)
#pragma unroll
                for (int nj = 0; nj < 4; nj++)
                    mma_tf32(acc[mi][nj], af[mi], bf[nj]);
        }
        buf = (buf == 2) ? 0 : buf + 1;
    }

#pragma unroll
    for (int mi = 0; mi < 4; mi++) {
        int row = mBase + warpM * 64 + mi * 16 + gid;
#pragma unroll
        for (int nj = 0; nj < 4; nj++) {
            int col = nC + warpN * 32 + nj * 8 + tig * 2;
            float2 v0 = make_float2(acc[mi][nj][0], acc[mi][nj][1]);
            float2 v1 = make_float2(acc[mi][nj][2], acc[mi][nj][3]);
            size_t o0 = (size_t)row * ldC + col;
            size_t o1 = (size_t)(row + 8) * ldC + col;
            if (EPI == 1) {
                float2 x0 = *reinterpret_cast<const float2*>(Aux + o0);
                float2 x1 = *reinterpret_cast<const float2*>(Aux + o1);
                v0.x += x0.x; v0.y += x0.y;
                v1.x += x1.x; v1.y += x1.y;
            }
            *reinterpret_cast<float2*>(C + o0) = v0;
            *reinterpret_cast<float2*>(C + o1) = v1;
        }
    }
}

template <int EPI>
__global__ void __launch_bounds__(256, 2) tgemm(
    const float* __restrict__ A, const float* __restrict__ B,
    float* __restrict__ C, const float* __restrict__ Aux, int K, int ldB, int ldC)
{
    gemm_core<EPI>(A, K, B, C, Aux, K, ldB, blockIdx.x * 128, ldC, blockIdx.x * 128);
}

// Split-K GEMM: grid (N/128, 2, 8). Partial z -> P + z*ROWS*ldC.
__global__ void __launch_bounds__(256, 2) tgemm_split(
    const float* __restrict__ A, int lda, const float* __restrict__ B,
    float* __restrict__ P, int kLen, int ldB, int ldC)
{
    int z = blockIdx.z;
    gemm_core<0>(A + (size_t)z * kLen, lda,
                 B + (size_t)z * kLen * ldB,
                 P + (size_t)z * ROWS * ldC, nullptr,
                 kLen, ldB, blockIdx.x * 128, ldC, blockIdx.x * 128);
}

// Split-K fused q/k/v: grid (24, 2, 8). kLen=512.
__global__ void __launch_bounds__(256, 2) tgemm_qkv_split(
    const float* __restrict__ A, const float* __restrict__ Bq,
    const float* __restrict__ Bk, const float* __restrict__ Bv, float* __restrict__ P)
{
    int bx = blockIdx.x, z = blockIdx.z;
    const float* B; int ldB, nB;
    if (bx < 16)      { B = Bq; ldB = 2048; nB = bx * 128; }
    else if (bx < 20) { B = Bk; ldB = 512;  nB = (bx - 16) * 128; }
    else              { B = Bv; ldB = 512;  nB = (bx - 20) * 128; }
    gemm_core<0>(A + (size_t)z * 512, 4096,
                 B + (size_t)z * 512 * ldB,
                 P + (size_t)z * ROWS * 3072, nullptr,
                 512, ldB, nB, 3072, bx * 128);
}

// Fused gate|up: grid (128, 2)
__global__ void __launch_bounds__(256, 2) tgemm_gu(
    const float* __restrict__ A, const float* __restrict__ Bg,
    const float* __restrict__ Bu, float* __restrict__ C)
{
    int bx = blockIdx.x;
    const float* B = (bx < 64) ? Bg : Bu;
    int nB = (bx & 63) * 128;
    gemm_core<0>(A, 2048, B, C, nullptr, 2048, INTER, nB, 2 * INTER, bx * 128);
}

// Reduce 8 split-K partials (+ optional residual), float4-vectorized.
template <bool RES>
__global__ void __launch_bounds__(256) reduce8_kernel(
    const float* __restrict__ P, const float* __restrict__ Aux,
    float* __restrict__ C, int nElems)
{
    int i = (blockIdx.x * 256 + threadIdx.x) * 4;
    if (i >= nElems) return;
    float4 r = *reinterpret_cast<const float4*>(P + i);
#pragma unroll
    for (int z = 1; z < 8; z++) {
        float4 a = *reinterpret_cast<const float4*>(P + (size_t)z * nElems + i);
        r.x += a.x; r.y += a.y; r.z += a.z; r.w += a.w;
    }
    if (RES) {
        float4 x = *reinterpret_cast<const float4*>(Aux + i);
        r.x += x.x; r.y += x.y; r.z += x.z; r.w += x.w;
    }
    *reinterpret_cast<float4*>(C + i) = r;
}

__global__ void __launch_bounds__(256) silu_mul_kernel(
    const float* __restrict__ gu, float* __restrict__ act)
{
    int i = blockIdx.x * 256 + threadIdx.x;
    int r = i >> 13, c = i & 8191;
    float g = gu[(size_t)r * (2 * INTER) + c];
    float u = gu[(size_t)r * (2 * INTER) + INTER + c];
    act[i] = (g / (1.f + expf(-g))) * u;
}

// ---------------------------------------------------------------------------
// Norm / copy / rope / gather / logsoftmax
// ---------------------------------------------------------------------------
__global__ void __launch_bounds__(256) rms_concat_kernel(
    const float* __restrict__ emb, const float* __restrict__ hs,
    const float* __restrict__ w_in, const float* __restrict__ w_hid,
    float* __restrict__ normed)
{
    const int row = blockIdx.x;
    const int tid = threadIdx.x;
    const float* x1 = emb + (size_t)row * HIDDEN;
    const float* x2 = hs + (size_t)row * HIDDEN;
    float s1 = 0.f, s2 = 0.f;
    for (int i = tid; i < HIDDEN; i += 256) {
        float a = x1[i]; s1 += a * a;
        float b = x2[i]; s2 += b * b;
    }
    float r1 = block_sum(s1);
    float r2 = block_sum(s2);
    float inv1 = rsqrtf(r1 / (float)HIDDEN + EPS);
    float inv2 = rsqrtf(r2 / (float)HIDDEN + EPS);
    float* o = normed + (size_t)row * (2 * HIDDEN);
    for (int i = tid; i < HIDDEN; i += 256) {
        o[i]          = x1[i] * inv1 * w_in[i];
        o[HIDDEN + i] = x2[i] * inv2 * w_hid[i];
    }
}

__global__ void __launch_bounds__(256) rms_kernel(
    const float* __restrict__ x, const float* __restrict__ w, float* __restrict__ y)
{
    const int row = blockIdx.x;
    const int tid = threadIdx.x;
    const float* xr = x + (size_t)row * HIDDEN;
    float s = 0.f;
    for (int i = tid; i < HIDDEN; i += 256) { float a = xr[i]; s += a * a; }
    float r = block_sum(s);
    float inv = rsqrtf(r / (float)HIDDEN + EPS);
    float* yr = y + (size_t)row * HIDDEN;
    for (int i = tid; i < HIDDEN; i += 256) yr[i] = xr[i] * inv * w[i];
}

__global__ void __launch_bounds__(256) gather_rms_kernel(
    const float* __restrict__ hs, const int* __restrict__ lt,
    const float* __restrict__ w, float* __restrict__ out_gathered,
    float* __restrict__ fn)
{
    const int row = blockIdx.x;
    const int tid = threadIdx.x;
    const int b = row >> 6;
    const int src_s = lt[row];
    const float* x = hs + ((size_t)b * SEQ + src_s) * HIDDEN;
    float s = 0.f;
    for (int i = tid; i < HIDDEN; i += 256) { float a = x[i]; s += a * a; }
    float r = block_sum(s);
    float inv = rsqrtf(r / (float)HIDDEN + EPS);
    float* og = out_gathered + (size_t)row * HIDDEN;
    float* fr = fn + (size_t)row * HIDDEN;
    for (int i = tid; i < HIDDEN; i += 256) {
        float a = x[i];
        og[i] = a;
        fr[i] = a * inv * w[i];
    }
}

__global__ void __launch_bounds__(256) copy_past_kernel(
    const float* __restrict__ past, float* __restrict__ present)
{
    const int idx = blockIdx.x * 256 + threadIdx.x;  // 2,097,152 float4
    const int lane = idx & 31;
    const int row = idx >> 5;
    const int t = row & 2047;
    const int bch = row >> 11;
    const float4* src = reinterpret_cast<const float4*>(past) + idx;
    float4* dst = reinterpret_cast<float4*>(present) + ((size_t)bch * TTOT + t) * 32 + lane;
    *dst = *src;
}

__global__ void __launch_bounds__(64) rope_store_kernel(
    float* __restrict__ qkv, const float* __restrict__ rope,
    const int* __restrict__ pos_ids, float* __restrict__ present)
{
    const int bs = blockIdx.x;
    const int h = blockIdx.y;
    const int d = threadIdx.x;
    const int b = bs >> 6, s = bs & 63;
    const int pos = pos_ids[bs];
    const float c = rope[(size_t)pos * 128 + d];
    const float sn = rope[(size_t)pos * 128 + 64 + d];
    float* row = qkv + (size_t)bs * 3072;
    if (h < 16) {
        float* base = row + h * 128;
        float x1 = base[d], x2 = base[d + 64];
        base[d] = x1 * c - x2 * sn;
        base[d + 64] = x2 * c + x1 * sn;
    } else if (h < 20) {
        const int kh = h - 16;
        const float* base = row + 2048 + kh * 128;
        float x1 = base[d], x2 = base[d + 64];
        float* dst = present + (((size_t)(b * 2 + 0) * NKV + kh) * TTOT + PAST + s) * HDIM;
        dst[d] = x1 * c - x2 * sn;
        dst[d + 64] = x2 * c + x1 * sn;
    } else {
        const int vh = h - 20;
        const float* base = row + 2560 + vh * 128;
        float* dst = present + (((size_t)(b * 2 + 1) * NKV + vh) * TTOT + PAST + s) * HDIM;
        dst[d] = base[d];
        dst[d + 64] = base[d + 64];
    }
}

// ---------------------------------------------------------------------------
// Attention, flash-decode split: grid (128, 6). Chunk cz covers 6 key-tiles
// (tiles cz*6 .. min(cz*6+6, 33)). Unnormalized acc + (m,l) partials.
// ---------------------------------------------------------------------------
#define QS_STRIDE 132
#define SC_STRIDE 65
#define ATTN_SMEM ((32 * QS_STRIDE + 64 * QS_STRIDE + 64 * QS_STRIDE + 32 * SC_STRIDE + 64) * 4)
#define ACC_CHUNK (ROWS * NQ * HDIM)
#define ML_CHUNK (ROWS * NQ * 2)
#define NCHUNK 6
#define TILES_TOTAL 33
#define TILES_PER_CHUNK 6

__global__ void __launch_bounds__(256) attn_part_kernel(
    const float* __restrict__ qkv, const float* __restrict__ kv,
    const int* __restrict__ ctx_len, float* __restrict__ pacc, float* __restrict__ pml)
{
    extern __shared__ float sm[];
    float* qs = sm;
    float* ks = qs + 32 * QS_STRIDE;
    float* vs = ks + 64 * QS_STRIDE;
    float* sc = vs + 64 * QS_STRIDE;
    float* corr = sc + 32 * SC_STRIDE;

    const int tid = threadIdx.x;
    const int blk = blockIdx.x;
    const int cz = blockIdx.y;
    const int qb = blk & 7;
    const int kvh = (blk >> 3) & 3;
    const int b = blk >> 5;

    for (int i = tid; i < 32 * 128; i += 256) {
        int ql = i >> 7, d = i & 127;
        int qid = qb * 32 + ql;
        int gi = qid >> 6, s = qid & 63;
        qs[ql * QS_STRIDE + d] =
            qkv[(size_t)(b * SEQ + s) * 3072 + (kvh * 4 + gi) * 128 + d];
    }

    float acc[16];
#pragma unroll
    for (int i = 0; i < 16; i++) acc[i] = 0.f;
    float m = -INFINITY, l = 0.f;

    const float* Kb = kv + (((size_t)(b * 2 + 0)) * NKV + kvh) * TTOT * HDIM;
    const float* Vb = kv + (((size_t)(b * 2 + 1)) * NKV + kvh) * TTOT * HDIM;
    const int ctx = ctx_len[b];

    const int ql_s = tid >> 3;
    const int ktg = tid & 7;
    const int qid_s = qb * 32 + ql_s;
    const int s_q = qid_s & 63;
    const int dg = (tid & 7) * 16;

    const int tile0 = cz * TILES_PER_CHUNK;
    const int tile1 = min(tile0 + TILES_PER_CHUNK, TILES_TOTAL);
    for (int ti = tile0; ti < tile1; ti++) {
        const int t0 = ti * 64;
        __syncthreads();
        for (int i = tid * 4; i < 64 * 128; i += 1024) {
            int r = i >> 7, d = i & 127;
            *reinterpret_cast<float4*>(&ks[r * QS_STRIDE + d]) =
                *reinterpret_cast<const float4*>(&Kb[(size_t)(t0 + r) * HDIM + d]);
            *reinterpret_cast<float4*>(&vs[r * QS_STRIDE + d]) =
                *reinterpret_cast<const float4*>(&Vb[(size_t)(t0 + r) * HDIM + d]);
        }
        __syncthreads();
        {
            const float* qrow = &qs[ql_s * QS_STRIDE];
#pragma unroll
            for (int j = 0; j < 8; j++) {
                int kt = ktg + 8 * j;
                const float* krow = &ks[kt * QS_STRIDE];
                float dot = 0.f;
#pragma unroll
                for (int d = 0; d < 128; d += 4) {
                    float4 qv = *reinterpret_cast<const float4*>(&qrow[d]);
                    float4 kk = *reinterpret_cast<const float4*>(&krow[d]);
                    dot = fmaf(qv.x, kk.x, dot);
                    dot = fmaf(qv.y, kk.y, dot);
                    dot = fmaf(qv.z, kk.z, dot);
                    dot = fmaf(qv.w, kk.w, dot);
                }
                int t = t0 + kt;
                bool valid = (t < PAST) ? (t < ctx) : ((t - PAST) <= s_q);
                sc[ql_s * SC_STRIDE + kt] =
                    valid ? dot * 0.08838834764831845f : -INFINITY;
            }
        }
        __syncthreads();
        if (tid < 32) {
            float mt = -INFINITY;
#pragma unroll 8
            for (int j = 0; j < 64; j++) mt = fmaxf(mt, sc[tid * SC_STRIDE + j]);
            float mnew = fmaxf(m, mt);
            float c, sum = 0.f;
            if (mnew == -INFINITY) {
                c = 1.f;
                for (int j = 0; j < 64; j++) sc[tid * SC_STRIDE + j] = 0.f;
            } else {
                c = __expf(m - mnew);
#pragma unroll 8
                for (int j = 0; j < 64; j++) {
                    float p = __expf(sc[tid * SC_STRIDE + j] - mnew);
                    sc[tid * SC_STRIDE + j] = p;
                    sum += p;
                }
            }
            l = l * c + sum;
            m = mnew;
            corr[tid] = c;
        }
        __syncthreads();
        {
            float c = corr[ql_s];
#pragma unroll
            for (int i = 0; i < 16; i++) acc[i] *= c;
            for (int kt = 0; kt < 64; kt++) {
                float p = sc[ql_s * SC_STRIDE + kt];
                const float* vrow = &vs[kt * QS_STRIDE + dg];
#pragma unroll
                for (int i = 0; i < 16; i += 4) {
                    float4 vv = *reinterpret_cast<const float4*>(&vrow[i]);
                    acc[i + 0] = fmaf(p, vv.x, acc[i + 0]);
                    acc[i + 1] = fmaf(p, vv.y, acc[i + 1]);
                    acc[i + 2] = fmaf(p, vv.z, acc[i + 2]);
                    acc[i + 3] = fmaf(p, vv.w, acc[i + 3]);
                }
            }
        }
    }
    if (tid < 32) {
        int qid = qb * 32 + tid;
        int gi = qid >> 6, s = qid & 63;
        int row = (b * SEQ + s) * NQ + (kvh * 4 + gi);
        pml[(size_t)cz * ML_CHUNK + row * 2 + 0] = m;
        pml[(size_t)cz * ML_CHUNK + row * 2 + 1] = l;
    }
    {
        int gi = qid_s >> 6, s = qid_s & 63;
        int row = (b * SEQ + s) * NQ + (kvh * 4 + gi);
        float* orow = pacc + (size_t)cz * ACC_CHUNK + (size_t)row * HDIM + dg;
#pragma unroll
        for (int i = 0; i < 16; i++) orow[i] = acc[i];
    }
}

// Merge NCHUNK chunks. grid 4096, block 128.
__global__ void __launch_bounds__(128) attn_merge_kernel(
    const float* __restrict__ pacc, const float* __restrict__ pml,
    float* __restrict__ out)
{
    const int row = blockIdx.x;
    const int d = threadIdx.x;
    float mv[NCHUNK], lv[NCHUNK];
    float mg = -INFINITY;
#pragma unroll
    for (int z = 0; z < NCHUNK; z++) {
        mv[z] = pml[(size_t)z * ML_CHUNK + row * 2 + 0];
        lv[z] = pml[(size_t)z * ML_CHUNK + row * 2 + 1];
        mg = fmaxf(mg, mv[z]);
    }
    float L = 0.f, a = 0.f;
    size_t o = (size_t)row * HDIM + d;
#pragma unroll
    for (int z = 0; z < NCHUNK; z++) {
        float w = __expf(mv[z] - mg);
        L += lv[z] * w;
        a += pacc[(size_t)z * ACC_CHUNK + o] * w;
    }
    out[o] = a / L;
}

__global__ void __launch_bounds__(256) logsoftmax_kernel(float* __restrict__ x)
{
    const int row = blockIdx.x;
    const int tid = threadIdx.x;
    float* xr = x + (size_t)row * VOCAB;
    float mv = -INFINITY;
    for (int i = tid; i < VOCAB; i += 256) mv = fmaxf(mv, xr[i]);
    float M = block_max(mv);
    float s = 0.f;
    for (int i = tid; i < VOCAB; i += 256) s += __expf(xr[i] - M);
    float S = block_sum(s);
    float lse = M + logf(S);
    for (int i = tid; i < VOCAB; i += 256) xr[i] = xr[i] - lse;
}

// ---------------------------------------------------------------------------
// Launch
// ---------------------------------------------------------------------------
extern "C" void kernel_launch(void* const* d_in, const int* in_sizes, int n_in,
                              void* d_out, int out_size)
{
    const float* inputs_embeds = (const float*)d_in[0];
    const float* past_kv       = (const float*)d_in[1];
    const float* rope          = (const float*)d_in[2];
    const int*   ctx_len       = (const int*)d_in[3];
    const int*   last_ids      = (const int*)d_in[5];
    const float* hsi           = (const float*)d_in[6];
    const float* hsd           = (const float*)d_in[7];
    const int*   pos_id        = (const int*)d_in[8];
    const float* W_fc   = (const float*)d_in[10];
    const float* W_q    = (const float*)d_in[11];
    const float* W_k    = (const float*)d_in[12];
    const float* W_v    = (const float*)d_in[13];
    const float* W_o    = (const float*)d_in[14];
    const float* W_gate = (const float*)d_in[15];
    const float* W_up   = (const float*)d_in[16];
    const float* W_down = (const float*)d_in[17];
    const float* W_lm   = (const float*)d_in[18];
    const float* w_hidden = (const float*)d_in[19];
    const float* w_input  = (const float*)d_in[20];
    const float* w_post   = (const float*)d_in[21];
    const float* w_final  = (const float*)d_in[22];

    float* out = (float*)d_out;
    float* out_logits   = out;
    float* out_gathered = out + LOGITS_ELEMS;
    float* out_present  = out + PRESENT_OFF;

    void* p;
    cudaGetSymbolAddress(&p, g_hs);     float* hs   = (float*)p;
    cudaGetSymbolAddress(&p, g_normed); float* nrm  = (float*)p;
    cudaGetSymbolAddress(&p, g_qkv);    float* qkv  = (float*)p;
    cudaGetSymbolAddress(&p, g_attn);   float* attnb= (float*)p;
    cudaGetSymbolAddress(&p, g_hn);     float* hn   = (float*)p;
    cudaGetSymbolAddress(&p, g_gu);     float* gu   = (float*)p;
    cudaGetSymbolAddress(&p, g_act);    float* actb = (float*)p;
    cudaGetSymbolAddress(&p, g_fn);     float* fnb  = (float*)p;
    cudaGetSymbolAddress(&p, g_part);   float* part = (float*)p;
    cudaGetSymbolAddress(&p, g_ml);     float* ml   = (float*)p;

    cudaFuncSetAttribute(attn_part_kernel, cudaFuncAttributeMaxDynamicSharedMemorySize, ATTN_SMEM);
    cudaFuncSetAttribute(tgemm<0>, cudaFuncAttributeMaxDynamicSharedMemorySize, GSMEM);
    cudaFuncSetAttribute(tgemm_split, cudaFuncAttributeMaxDynamicSharedMemorySize, GSMEM);
    cudaFuncSetAttribute(tgemm_qkv_split, cudaFuncAttributeMaxDynamicSharedMemorySize, GSMEM);
    cudaFuncSetAttribute(tgemm_gu, cudaFuncAttributeMaxDynamicSharedMemorySize, GSMEM);

    // 1. hs = draft + hsi @ W_fc   (split-K 8: 256 blocks)
    tgemm_split<<<dim3(16, 2, 8), 256, GSMEM>>>(hsi, 6144, W_fc, part, 768, HIDDEN, HIDDEN);
    reduce8_kernel<true><<<512, 256>>>(part, hsd, hs, ROWS * HIDDEN);
    // 2. normed
    rms_concat_kernel<<<ROWS, 256>>>(inputs_embeds, hs, w_input, w_hidden, nrm);
    // 3. fused qkv (split-K 8: 384 blocks)
    tgemm_qkv_split<<<dim3(24, 2, 8), 256, GSMEM>>>(nrm, W_q, W_k, W_v, part);
    reduce8_kernel<false><<<768, 256>>>(part, nullptr, qkv, ROWS * 3072);
    // 4. present
    copy_past_kernel<<<8192, 256>>>(past_kv, out_present);
    rope_store_kernel<<<dim3(256, 24), 64>>>(qkv, rope, pos_id, out_present);
    // 5. attention (flash-decode over 6 T-chunks: 768 blocks)
    attn_part_kernel<<<dim3(128, NCHUNK), 256, ATTN_SMEM>>>(qkv, out_present, ctx_len, part, ml);
    attn_merge_kernel<<<4096, 128>>>(part, ml, attnb);
    // 6. hs += attn @ W_o  (split-K 8: 256 blocks)
    tgemm_split<<<dim3(16, 2, 8), 256, GSMEM>>>(attnb, 2048, W_o, part, 256, HIDDEN, HIDDEN);
    reduce8_kernel<true><<<512, 256>>>(part, hs, hs, ROWS * HIDDEN);
    // 7. MLP
    rms_kernel<<<ROWS, 256>>>(hs, w_post, hn);
    tgemm_gu<<<dim3(128, 2), 256, GSMEM>>>(hn, W_gate, W_up, gu);
    silu_mul_kernel<<<8192, 256>>>(gu, actb);
    tgemm_split<<<dim3(16, 2, 8), 256, GSMEM>>>(actb, INTER, W_down, part, 1024, HIDDEN, HIDDEN);
    reduce8_kernel<true><<<512, 256>>>(part, hs, hs, ROWS * HIDDEN);
    // 8. gather + final norm
    gather_rms_kernel<<<ROWS, 256>>>(hs, last_ids, w_final, out_gathered, fnb);
    // 9. LM head + log_softmax
    tgemm<0><<<dim3(250, 2), 256, GSMEM>>>(fnb, W_lm, out_logits, nullptr, 2048, VOCAB, VOCAB);
    logsoftmax_kernel<<<ROWS, 256>>>(out_logits);
}